// round 1
// baseline (speedup 1.0000x reference)
#include <cuda_runtime.h>
#include <cstdint>

#define BATCH 2
#define CH    64
#define DD    20
#define HH    20
#define WW    20
#define NN    8000
#define SK    68   // smem row stride (floats), padded for bank-conflict-free frag reads

// Scratch: q0/k0/v projections, layout [b][n][c], values pre-rounded to tf32.
__device__ float g_Q[BATCH * NN * CH];
__device__ float g_K[BATCH * NN * CH];
__device__ float g_V[BATCH * NN * CH];

__device__ __forceinline__ uint32_t f2tf(float f) {
    uint32_t u;
    asm("cvt.rna.tf32.f32 %0, %1;" : "=r"(u) : "f"(f));
    return u;
}

// ---------------------------------------------------------------------------
// Conv kernel: Out[b][n][co] = bias[co] + sum_{ci,t} W[co][ci][t] * X[ci,t][n]
// as a 64(co) x 64(n) x 192(k) GEMM tile per block. blockIdx.z selects which
// conv (0=q taps h, 1=k taps d, 2=v taps w). All three weight tensors flatten
// identically to [co][ci*3+t].
// ---------------------------------------------------------------------------
__global__ __launch_bounds__(128) void conv_kernel(
    const float* __restrict__ x,
    const float* __restrict__ qw, const float* __restrict__ qb,
    const float* __restrict__ kw, const float* __restrict__ kbias,
    const float* __restrict__ vw, const float* __restrict__ vb)
{
    const int nt = blockIdx.x;   // n tile (125)
    const int b  = blockIdx.y;   // batch (2)
    const int cv = blockIdx.z;   // conv id (3)
    const float* Wp = (cv == 0) ? qw : ((cv == 1) ? kw : vw);
    const float* Bp = (cv == 0) ? qb : ((cv == 1) ? kbias : vb);
    float* Out = (cv == 0) ? g_Q : ((cv == 1) ? g_K : g_V);
    const int n0  = nt * 64;
    const int tid = threadIdx.x;

    __shared__ float Ws[16][SK];  // k-chunk x co
    __shared__ float Xs[16][SK];  // k-chunk x n

    const int tn = (tid & 15) * 4;  // this thread's n offset (4 n)
    const int tc = (tid >> 4) * 8;  // this thread's co offset (8 co)
    float acc[8][4];
#pragma unroll
    for (int i = 0; i < 8; i++)
#pragma unroll
        for (int j = 0; j < 4; j++) acc[i][j] = 0.f;

    // staging assignment: thread stages 8 n of one k-row per chunk
    const int ks = tid >> 3;        // k row 0..15
    const int nb = (tid & 7) * 8;   // n base
    int pd[8], ph[8], pw[8];
#pragma unroll
    for (int j = 0; j < 8; j++) {
        int n = n0 + nb + j;
        pd[j] = n / 400;
        int rem = n - pd[j] * 400;
        ph[j] = rem / 20;
        pw[j] = rem - ph[j] * 20;
    }

    for (int k0 = 0; k0 < 192; k0 += 16) {
        // weights -> Ws[k][co]  (coalesced float4 from [co][k])
#pragma unroll
        for (int i = 0; i < 2; i++) {
            int idx4 = tid * 2 + i;
            int co = idx4 >> 2, k4 = (idx4 & 3) * 4;
            float4 wv = *reinterpret_cast<const float4*>(Wp + co * 192 + k0 + k4);
            Ws[k4 + 0][co] = wv.x; Ws[k4 + 1][co] = wv.y;
            Ws[k4 + 2][co] = wv.z; Ws[k4 + 3][co] = wv.w;
        }
        // im2col X -> Xs[k][n]
        {
            int kk = k0 + ks;
            int ci = kk / 3;
            int dt = kk - ci * 3 - 1;   // tap offset -1/0/+1
#pragma unroll
            for (int j = 0; j < 8; j++) {
                int d = pd[j], h = ph[j], w = pw[j];
                if (cv == 0) h += dt; else if (cv == 1) d += dt; else w += dt;
                unsigned cd = (cv == 0) ? (unsigned)h : ((cv == 1) ? (unsigned)d : (unsigned)w);
                float val = 0.f;
                if (cd < 20u)
                    val = x[((b * CH + ci) * DD + d) * 400 + h * 20 + w];
                Xs[ks][nb + j] = val;
            }
        }
        __syncthreads();
#pragma unroll
        for (int kk = 0; kk < 16; kk++) {
            float4 xr = *reinterpret_cast<const float4*>(&Xs[kk][tn]);
            float wr[8];
#pragma unroll
            for (int i = 0; i < 8; i++) wr[i] = Ws[kk][tc + i];
#pragma unroll
            for (int i = 0; i < 8; i++) {
                acc[i][0] += wr[i] * xr.x; acc[i][1] += wr[i] * xr.y;
                acc[i][2] += wr[i] * xr.z; acc[i][3] += wr[i] * xr.w;
            }
        }
        __syncthreads();
    }
#pragma unroll
    for (int i = 0; i < 8; i++) {
        float bias = Bp[tc + i];
#pragma unroll
        for (int j = 0; j < 4; j++) {
            int n = n0 + tn + j;
            Out[(b * NN + n) * CH + tc + i] = __uint_as_float(f2tf(acc[i][j] + bias));
        }
    }
}

// ---------------------------------------------------------------------------
// Attention kernel (flash-style, no online max needed — scores are O(10)):
//   per CTA: 64 queries (m), loop 125 key tiles of 64 (n).
//   QK: S[m][n] = Q[m][:].K[n][:]   (tf32 mma, A=Q frags persistent in regs)
//   P = exp(S); den[m] += row-sum(P);  P staged to smem (reusing K buffer)
//   PV: O[m][c] += P[m][:] V[:][c]  (tf32 mma, fp32 accum)
//   final: out[b][c][m] = O[m][c] / den[m]
// ---------------------------------------------------------------------------
#define MMA_TF32(d, a, b0_, b1_)                                              \
    asm volatile("mma.sync.aligned.m16n8k8.row.col.f32.tf32.tf32.f32 "        \
                 "{%0,%1,%2,%3},{%4,%5,%6,%7},{%8,%9},{%0,%1,%2,%3};\n"       \
                 : "+f"(d[0]), "+f"(d[1]), "+f"(d[2]), "+f"(d[3])             \
                 : "r"(a[0]), "r"(a[1]), "r"(a[2]), "r"(a[3]),                \
                   "r"(b0_), "r"(b1_))

__global__ __launch_bounds__(128) void attn_kernel(float* __restrict__ out)
{
    __shared__ uint32_t KP[64 * SK];  // K tile, then reused as P tile
    __shared__ uint32_t Vs[64 * SK];  // V tile

    const int tid  = threadIdx.x;
    const int warp = tid >> 5, lane = tid & 31;
    const int g = lane >> 2, r = lane & 3;  // groupID, threadID_in_group
    const int b  = blockIdx.y;
    const int m0 = blockIdx.x * 64;
    const int mw = warp * 16;               // warp's m strip inside tile

    const float* Qg = g_Q + (size_t)(b * NN + m0) * CH;
    const float* Kg = g_K + (size_t)b * NN * CH;
    const float* Vg = g_V + (size_t)b * NN * CH;

    // ---- stage Q tile through smem, load persistent A-frags (tf32 already) ----
#pragma unroll
    for (int i = 0; i < 8; i++) {
        int flat = i * 512 + tid * 4;
        int row = flat >> 6, col = flat & 63;
        *reinterpret_cast<uint4*>(&KP[row * SK + col]) =
            *reinterpret_cast<const uint4*>(Qg + row * CH + col);
    }
    __syncthreads();
    uint32_t qa[8][4];
#pragma unroll
    for (int kb = 0; kb < 8; kb++) {
        qa[kb][0] = KP[(mw + g) * SK + kb * 8 + r];
        qa[kb][1] = KP[(mw + 8 + g) * SK + kb * 8 + r];
        qa[kb][2] = KP[(mw + g) * SK + kb * 8 + r + 4];
        qa[kb][3] = KP[(mw + 8 + g) * SK + kb * 8 + r + 4];
    }
    __syncthreads();

    float oacc[8][4];
#pragma unroll
    for (int i = 0; i < 8; i++)
#pragma unroll
        for (int j = 0; j < 4; j++) oacc[i][j] = 0.f;
    float den0 = 0.f, den1 = 0.f;

    for (int n0 = 0; n0 < NN; n0 += 64) {
        // ---- stage K, V tiles (coalesced float4) ----
#pragma unroll
        for (int i = 0; i < 8; i++) {
            int flat = i * 512 + tid * 4;
            int row = flat >> 6, col = flat & 63;
            *reinterpret_cast<uint4*>(&KP[row * SK + col]) =
                *reinterpret_cast<const uint4*>(Kg + (size_t)(n0 + row) * CH + col);
            *reinterpret_cast<uint4*>(&Vs[row * SK + col]) =
                *reinterpret_cast<const uint4*>(Vg + (size_t)(n0 + row) * CH + col);
        }
        __syncthreads();

        // ---- QK: S = Q . K^T  (B-frag: B[k=c][n] = K[n][c]) ----
        float s[8][4];
#pragma unroll
        for (int nb = 0; nb < 8; nb++) {
#pragma unroll
            for (int j = 0; j < 4; j++) s[nb][j] = 0.f;
#pragma unroll
            for (int kb = 0; kb < 8; kb++) {
                uint32_t b0 = KP[(nb * 8 + g) * SK + kb * 8 + r];
                uint32_t b1 = KP[(nb * 8 + g) * SK + kb * 8 + r + 4];
                MMA_TF32(s[nb], qa[kb], b0, b1);
            }
        }
        __syncthreads();  // done reading K tile

        // ---- exp + denom + stage P (fragment layout: c0,c1 row g / c2,c3 row g+8) ----
#pragma unroll
        for (int nb = 0; nb < 8; nb++) {
            float p0 = __expf(s[nb][0]), p1 = __expf(s[nb][1]);
            float p2 = __expf(s[nb][2]), p3 = __expf(s[nb][3]);
            den0 += p0 + p1;
            den1 += p2 + p3;
            KP[(mw + g) * SK + nb * 8 + 2 * r]         = f2tf(p0);
            KP[(mw + g) * SK + nb * 8 + 2 * r + 1]     = f2tf(p1);
            KP[(mw + 8 + g) * SK + nb * 8 + 2 * r]     = f2tf(p2);
            KP[(mw + 8 + g) * SK + nb * 8 + 2 * r + 1] = f2tf(p3);
        }
        __syncthreads();  // P tile ready

        // ---- PV: O += P . V  (A from P smem, B[k=n][c] = V[n][c]) ----
#pragma unroll
        for (int kb = 0; kb < 8; kb++) {
            uint32_t a[4];
            a[0] = KP[(mw + g) * SK + kb * 8 + r];
            a[1] = KP[(mw + 8 + g) * SK + kb * 8 + r];
            a[2] = KP[(mw + g) * SK + kb * 8 + r + 4];
            a[3] = KP[(mw + 8 + g) * SK + kb * 8 + r + 4];
#pragma unroll
            for (int cb = 0; cb < 8; cb++) {
                uint32_t b0 = Vs[(kb * 8 + r) * SK + cb * 8 + g];
                uint32_t b1 = Vs[(kb * 8 + r + 4) * SK + cb * 8 + g];
                MMA_TF32(oacc[cb], a, b0, b1);
            }
        }
        __syncthreads();  // safe to overwrite K/V/P next iteration
    }

    // ---- reduce denominators across the 4 lanes sharing each m row ----
    den0 += __shfl_xor_sync(0xffffffffu, den0, 1);
    den0 += __shfl_xor_sync(0xffffffffu, den0, 2);
    den1 += __shfl_xor_sync(0xffffffffu, den1, 1);
    den1 += __shfl_xor_sync(0xffffffffu, den1, 2);
    const float i0 = 1.f / den0, i1 = 1.f / den1;

    // ---- write out[b][c][m] ----
    const int m = m0 + mw + g;
#pragma unroll
    for (int cb = 0; cb < 8; cb++) {
        int c = cb * 8 + 2 * r;
        out[((size_t)b * CH + c    ) * NN + m]     = oacc[cb][0] * i0;
        out[((size_t)b * CH + c + 1) * NN + m]     = oacc[cb][1] * i0;
        out[((size_t)b * CH + c    ) * NN + m + 8] = oacc[cb][2] * i1;
        out[((size_t)b * CH + c + 1) * NN + m + 8] = oacc[cb][3] * i1;
    }
}

extern "C" void kernel_launch(void* const* d_in, const int* in_sizes, int n_in,
                              void* d_out, int out_size)
{
    const float* x  = (const float*)d_in[0];
    const float* qw = (const float*)d_in[1];
    const float* qb = (const float*)d_in[2];
    const float* kw = (const float*)d_in[3];
    const float* kb = (const float*)d_in[4];
    const float* vw = (const float*)d_in[5];
    const float* vb = (const float*)d_in[6];
    float* out = (float*)d_out;

    conv_kernel<<<dim3(125, 2, 3), 128>>>(x, qw, qb, kw, kb, vw, vb);
    attn_kernel<<<dim3(125, 2), 128>>>(out);
}

// round 4
// speedup vs baseline: 1.7891x; 1.7891x over previous
#include <cuda_runtime.h>
#include <cuda_fp16.h>
#include <cstdint>

#define BATCH 2
#define CH    64
#define DD    20
#define NN    8000
#define SK    68
#define PSCALE 3.814697265625e-6f   // 2^-18: exact, cancels in num/den; keeps exp() in fp16 range
                                    // (scores can reach ~20; exp(20)*2^-18 = 1850 << 65504)

// Projections in fp16. g_Q,g_K: [b][n][c] with channel-words permuted for LDS.128 frags.
// g_V: [b][c][n] with key-words permuted within each 64-block.
__device__ __align__(256) __half g_Qh[BATCH * NN * CH];
__device__ __align__(256) __half g_Kh[BATCH * NN * CH];
__device__ __align__(256) __half g_Vh[BATCH * NN * CH];

// word permutation: natural b32-word w (2 halfs) -> position such that each thread's
// (b0,b1) frag words for a k16-pair are 16B-contiguous (one LDS.128 = B for 2 MMAs)
__device__ __forceinline__ int permw(int w) {
    int k16 = w >> 3, j = w & 7;
    return (k16 >> 1) * 16 + (j & 3) * 4 + ((j >> 2) << 1) + (k16 & 1);
}

// ---------------------------------------------------------------------------
// Conv kernel: GEMM-style, outputs fp16 with baked-in permutations.
// ---------------------------------------------------------------------------
__global__ __launch_bounds__(128) void conv_kernel(
    const float* __restrict__ x,
    const float* __restrict__ qw, const float* __restrict__ qb,
    const float* __restrict__ kw, const float* __restrict__ kbias,
    const float* __restrict__ vw, const float* __restrict__ vb)
{
    const int nt = blockIdx.x, b = blockIdx.y, cv = blockIdx.z;
    const float* Wp = (cv == 0) ? qw : ((cv == 1) ? kw : vw);
    const float* Bp = (cv == 0) ? qb : ((cv == 1) ? kbias : vb);
    const int n0 = nt * 64, tid = threadIdx.x;

    __shared__ float Ws[16][SK];
    __shared__ float Xs[16][SK];

    const int tn = (tid & 15) * 4;
    const int tc = (tid >> 4) * 8;
    float acc[8][4];
#pragma unroll
    for (int i = 0; i < 8; i++)
#pragma unroll
        for (int j = 0; j < 4; j++) acc[i][j] = 0.f;

    const int ks = tid >> 3;
    const int nb = (tid & 7) * 8;
    int pd[8], ph[8], pw[8];
#pragma unroll
    for (int j = 0; j < 8; j++) {
        int n = n0 + nb + j;
        pd[j] = n / 400;
        int rem = n - pd[j] * 400;
        ph[j] = rem / 20;
        pw[j] = rem - ph[j] * 20;
    }

    for (int k0 = 0; k0 < 192; k0 += 16) {
#pragma unroll
        for (int i = 0; i < 2; i++) {
            int idx4 = tid * 2 + i;
            int co = idx4 >> 2, k4 = (idx4 & 3) * 4;
            float4 wv = *reinterpret_cast<const float4*>(Wp + co * 192 + k0 + k4);
            Ws[k4 + 0][co] = wv.x; Ws[k4 + 1][co] = wv.y;
            Ws[k4 + 2][co] = wv.z; Ws[k4 + 3][co] = wv.w;
        }
        {
            int kk = k0 + ks;
            int ci = kk / 3;
            int dt = kk - ci * 3 - 1;
#pragma unroll
            for (int j = 0; j < 8; j++) {
                int d = pd[j], h = ph[j], w = pw[j];
                if (cv == 0) h += dt; else if (cv == 1) d += dt; else w += dt;
                unsigned cd = (cv == 0) ? (unsigned)h : ((cv == 1) ? (unsigned)d : (unsigned)w);
                float val = 0.f;
                if (cd < 20u)
                    val = x[((b * CH + ci) * DD + d) * 400 + h * 20 + w];
                Xs[ks][nb + j] = val;
            }
        }
        __syncthreads();
#pragma unroll
        for (int kk = 0; kk < 16; kk++) {
            float4 xr = *reinterpret_cast<const float4*>(&Xs[kk][tn]);
            float wr[8];
#pragma unroll
            for (int i = 0; i < 8; i++) wr[i] = Ws[kk][tc + i];
#pragma unroll
            for (int i = 0; i < 8; i++) {
                acc[i][0] += wr[i] * xr.x; acc[i][1] += wr[i] * xr.y;
                acc[i][2] += wr[i] * xr.z; acc[i][3] += wr[i] * xr.w;
            }
        }
        __syncthreads();
    }
#pragma unroll
    for (int i = 0; i < 8; i++) {
        const int co = tc + i;
        const float bias = Bp[co];
#pragma unroll
        for (int j = 0; j < 4; j++) {
            const int n = n0 + tn + j;
            const __half hv = __float2half_rn(acc[i][j] + bias);
            if (cv == 2) {
                int nl = tn + j;
                int np = permw(nl >> 1) * 2 + (nl & 1);
                g_Vh[((size_t)b * CH + co) * NN + n0 + np] = hv;
            } else {
                int cp = permw(co >> 1) * 2 + (co & 1);
                (cv ? g_Kh : g_Qh)[((size_t)b * NN + n) * CH + cp] = hv;
            }
        }
    }
}

// ---------------------------------------------------------------------------
// Attention kernel: fp16 mma.sync, FA2 S->P register reuse, cp.async pipeline.
// ---------------------------------------------------------------------------
__device__ __forceinline__ uint32_t smem_u32(const void* p) {
    uint32_t a;
    asm("{ .reg .u64 t; cvta.to.shared.u64 t, %1; cvt.u32.u64 %0, t; }" : "=r"(a) : "l"(p));
    return a;
}

#define MMA16(d, a, b0_, b1_)                                                 \
    asm volatile("mma.sync.aligned.m16n8k16.row.col.f32.f16.f16.f32 "         \
                 "{%0,%1,%2,%3},{%4,%5,%6,%7},{%8,%9},{%0,%1,%2,%3};"         \
                 : "+f"((d)[0]), "+f"((d)[1]), "+f"((d)[2]), "+f"((d)[3])     \
                 : "r"((a)[0]), "r"((a)[1]), "r"((a)[2]), "r"((a)[3]),        \
                   "r"(b0_), "r"(b1_))

#define CP16(dst, src)                                                        \
    asm volatile("cp.async.cg.shared.global [%0], [%1], 16;" :: "r"(dst), "l"(src))
#define CP_COMMIT() asm volatile("cp.async.commit_group;" ::: "memory")
#define CP_WAIT1()  asm volatile("cp.async.wait_group 1;" ::: "memory")

__device__ __forceinline__ uint4 lds128(uint32_t a) {
    uint4 v;
    asm volatile("ld.shared.v4.b32 {%0,%1,%2,%3}, [%4];"
                 : "=r"(v.x), "=r"(v.y), "=r"(v.z), "=r"(v.w) : "r"(a));
    return v;
}

__device__ __forceinline__ uint32_t packh(float a, float b) {
    __half2 h = __floats2half2_rn(a, b);
    return *reinterpret_cast<uint32_t*>(&h);
}

// dynamic smem layout (bytes): K[2] @0 (2x12288), V[2] @24576, Q @49152; total 61440
#define ROWB  192    // 64 halfs padded to 96 halfs = 192B (conflict-free LDS.128)
#define KOFF  0
#define VOFF  24576
#define QOFF  49152

__global__ __launch_bounds__(128, 2) void attn_kernel(float* __restrict__ out)
{
    extern __shared__ __align__(16) uint8_t sm[];
    const int tid = threadIdx.x;
    const int warp = tid >> 5, lane = tid & 31;
    const int g = lane >> 2, r = lane & 3;
    const int b = blockIdx.y;
    const int m0 = (int)(((unsigned)blockIdx.x * 7936u) / 147u);  // overlapping tiles, 1 wave
    const int mw = warp * 16;
    const int row = tid >> 1, hb = tid & 1;    // staging: 64B chunk per thread per buffer

    const uint32_t sb = smem_u32(sm);
    const uint32_t kd = sb + KOFF + row * ROWB + hb * 64;
    const uint32_t vd = sb + VOFF + row * ROWB + hb * 64;
    const uint8_t* kg = (const uint8_t*)g_Kh + ((size_t)b * NN + row) * 128 + hb * 64;
    const uint8_t* vg = (const uint8_t*)g_Vh + ((size_t)(b * CH) + row) * (NN * 2) + hb * 64;

    // prologue: cp.async tiles 0 and 1
#pragma unroll
    for (int stg = 0; stg < 2; stg++) {
#pragma unroll
        for (int i = 0; i < 4; i++) CP16(kd + stg * 12288 + i * 16, kg + (size_t)stg * 8192 + i * 16);
#pragma unroll
        for (int i = 0; i < 4; i++) CP16(vd + stg * 12288 + i * 16, vg + (size_t)stg * 128 + i * 16);
        CP_COMMIT();
    }

    // stage Q tile + load persistent A-fragments
    {
        const uint4* qs = (const uint4*)((const uint8_t*)g_Qh + ((size_t)b * NN + m0 + row) * 128 + hb * 64);
        uint4* qdp = (uint4*)(sm + QOFF + row * ROWB + hb * 64);
        qdp[0] = qs[0]; qdp[1] = qs[1]; qdp[2] = qs[2]; qdp[3] = qs[3];
    }
    __syncthreads();
    uint32_t qa[4][4];
#pragma unroll
    for (int kp = 0; kp < 2; kp++)
#pragma unroll
        for (int h = 0; h < 2; h++) {
            uint4 v = lds128(sb + QOFF + (mw + h * 8 + g) * ROWB + kp * 64 + r * 16);
            qa[2 * kp][h]     = v.x;
            qa[2 * kp + 1][h] = v.y;
            qa[2 * kp][h + 2]     = v.z;
            qa[2 * kp + 1][h + 2] = v.w;
        }

    float oacc[8][4];
#pragma unroll
    for (int i = 0; i < 8; i++)
#pragma unroll
        for (int j = 0; j < 4; j++) oacc[i][j] = 0.f;
    float den0 = 0.f, den1 = 0.f;

#pragma unroll 1
    for (int t = 0; t < 125; t++) {
        CP_WAIT1();
        __syncthreads();   // tile t data visible; prior tile's reads complete
        const uint32_t ks = sb + KOFF + (t & 1) * 12288;
        const uint32_t vs = sb + VOFF + (t & 1) * 12288;

        // ---- QK: S[m16 x 64keys] ----
        float s[8][4];
#pragma unroll
        for (int nb = 0; nb < 8; nb++) {
#pragma unroll
            for (int j = 0; j < 4; j++) s[nb][j] = 0.f;
            const uint32_t rb = ks + (nb * 8 + g) * ROWB + r * 16;
#pragma unroll
            for (int kp = 0; kp < 2; kp++) {
                uint4 bv = lds128(rb + kp * 64);
                MMA16(s[nb], qa[2 * kp],     bv.x, bv.z);
                MMA16(s[nb], qa[2 * kp + 1], bv.y, bv.w);
            }
        }

        // ---- exp + denom; S-frags become PV A-frags in registers (FA2 trick) ----
        uint32_t pa[4][4];
#pragma unroll
        for (int kb = 0; kb < 4; kb++) {
            float e00 = fminf(__expf(s[2 * kb][0]) * PSCALE, 65000.f);
            float e01 = fminf(__expf(s[2 * kb][1]) * PSCALE, 65000.f);
            float e02 = fminf(__expf(s[2 * kb][2]) * PSCALE, 65000.f);
            float e03 = fminf(__expf(s[2 * kb][3]) * PSCALE, 65000.f);
            float e10 = fminf(__expf(s[2 * kb + 1][0]) * PSCALE, 65000.f);
            float e11 = fminf(__expf(s[2 * kb + 1][1]) * PSCALE, 65000.f);
            float e12 = fminf(__expf(s[2 * kb + 1][2]) * PSCALE, 65000.f);
            float e13 = fminf(__expf(s[2 * kb + 1][3]) * PSCALE, 65000.f);
            den0 += e00 + e01 + e10 + e11;
            den1 += e02 + e03 + e12 + e13;
            pa[kb][0] = packh(e00, e01);   // row g,   k-lo
            pa[kb][1] = packh(e02, e03);   // row g+8, k-lo
            pa[kb][2] = packh(e10, e11);   // row g,   k-hi
            pa[kb][3] = packh(e12, e13);   // row g+8, k-hi
        }

        // ---- PV: O += P . V^T ----
#pragma unroll
        for (int cb = 0; cb < 8; cb++) {
            const uint32_t rb = vs + (cb * 8 + g) * ROWB + r * 16;
#pragma unroll
            for (int kp = 0; kp < 2; kp++) {
                uint4 bv = lds128(rb + kp * 64);
                MMA16(oacc[cb], pa[2 * kp],     bv.x, bv.z);
                MMA16(oacc[cb], pa[2 * kp + 1], bv.y, bv.w);
            }
        }

        __syncthreads();   // all warps done reading stage (t&1) before refill
        if (t + 2 < 125) {
            const uint32_t kd2 = kd + (t & 1) * 12288;
            const uint32_t vd2 = vd + (t & 1) * 12288;
            const uint8_t* kg2 = kg + (size_t)(t + 2) * 8192;
            const uint8_t* vg2 = vg + (size_t)(t + 2) * 128;
#pragma unroll
            for (int i = 0; i < 4; i++) CP16(kd2 + i * 16, kg2 + i * 16);
#pragma unroll
            for (int i = 0; i < 4; i++) CP16(vd2 + i * 16, vg2 + i * 16);
        }
        CP_COMMIT();       // commit (possibly empty) to keep wait_group invariant
    }

    // ---- denominators: reduce over the 4 lanes sharing each m row ----
    den0 += __shfl_xor_sync(0xffffffffu, den0, 1);
    den0 += __shfl_xor_sync(0xffffffffu, den0, 2);
    den1 += __shfl_xor_sync(0xffffffffu, den1, 1);
    den1 += __shfl_xor_sync(0xffffffffu, den1, 2);
    const float i0 = 1.f / den0, i1 = 1.f / den1;

    // ---- out[b][c][m] ----
    const int m = m0 + mw + g;
#pragma unroll
    for (int cb = 0; cb < 8; cb++) {
        int c = cb * 8 + 2 * r;
        out[((size_t)b * CH + c    ) * NN + m]     = oacc[cb][0] * i0;
        out[((size_t)b * CH + c + 1) * NN + m]     = oacc[cb][1] * i0;
        out[((size_t)b * CH + c    ) * NN + m + 8] = oacc[cb][2] * i1;
        out[((size_t)b * CH + c + 1) * NN + m + 8] = oacc[cb][3] * i1;
    }
}

extern "C" void kernel_launch(void* const* d_in, const int* in_sizes, int n_in,
                              void* d_out, int out_size)
{
    const float* x  = (const float*)d_in[0];
    const float* qw = (const float*)d_in[1];
    const float* qb = (const float*)d_in[2];
    const float* kw = (const float*)d_in[3];
    const float* kb = (const float*)d_in[4];
    const float* vw = (const float*)d_in[5];
    const float* vb = (const float*)d_in[6];
    float* out = (float*)d_out;

    cudaFuncSetAttribute(attn_kernel, cudaFuncAttributeMaxDynamicSharedMemorySize, 61440);
    conv_kernel<<<dim3(125, 2, 3), 128>>>(x, qw, qb, kw, kb, vw, vb);
    attn_kernel<<<dim3(148, 2), 128, 61440>>>(out);
}

// round 6
// speedup vs baseline: 2.1474x; 1.2003x over previous
#include <cuda_runtime.h>
#include <cuda_fp16.h>
#include <cstdint>

#define BATCH 2
#define CH    64
#define DD    20
#define NN    8000
#define SK    68

// Projections in fp16. g_Q,g_K: [b][n][c] with channel-words permuted for LDS.128 frags.
// g_V: [b][c][n] with key-words permuted within each 64-block.
__device__ __align__(256) __half g_Qh[BATCH * NN * CH];
__device__ __align__(256) __half g_Kh[BATCH * NN * CH];
__device__ __align__(256) __half g_Vh[BATCH * NN * CH];

// word permutation: natural b32-word w (2 halfs) -> position such that each thread's
// (b0,b1) frag words for a k16-pair are 16B-contiguous (one LDS.128 = B for 2 MMAs)
__device__ __forceinline__ int permw(int w) {
    int k16 = w >> 3, j = w & 7;
    return (k16 >> 1) * 16 + (j & 3) * 4 + ((j >> 2) << 1) + (k16 & 1);
}

// ---------------------------------------------------------------------------
// Conv kernel (unchanged from R4)
// ---------------------------------------------------------------------------
__global__ __launch_bounds__(128) void conv_kernel(
    const float* __restrict__ x,
    const float* __restrict__ qw, const float* __restrict__ qb,
    const float* __restrict__ kw, const float* __restrict__ kbias,
    const float* __restrict__ vw, const float* __restrict__ vb)
{
    const int nt = blockIdx.x, b = blockIdx.y, cv = blockIdx.z;
    const float* Wp = (cv == 0) ? qw : ((cv == 1) ? kw : vw);
    const float* Bp = (cv == 0) ? qb : ((cv == 1) ? kbias : vb);
    const int n0 = nt * 64, tid = threadIdx.x;

    __shared__ float Ws[16][SK];
    __shared__ float Xs[16][SK];

    const int tn = (tid & 15) * 4;
    const int tc = (tid >> 4) * 8;
    float acc[8][4];
#pragma unroll
    for (int i = 0; i < 8; i++)
#pragma unroll
        for (int j = 0; j < 4; j++) acc[i][j] = 0.f;

    const int ks = tid >> 3;
    const int nb = (tid & 7) * 8;
    int pd[8], ph[8], pw[8];
#pragma unroll
    for (int j = 0; j < 8; j++) {
        int n = n0 + nb + j;
        pd[j] = n / 400;
        int rem = n - pd[j] * 400;
        ph[j] = rem / 20;
        pw[j] = rem - ph[j] * 20;
    }

    for (int k0 = 0; k0 < 192; k0 += 16) {
#pragma unroll
        for (int i = 0; i < 2; i++) {
            int idx4 = tid * 2 + i;
            int co = idx4 >> 2, k4 = (idx4 & 3) * 4;
            float4 wv = *reinterpret_cast<const float4*>(Wp + co * 192 + k0 + k4);
            Ws[k4 + 0][co] = wv.x; Ws[k4 + 1][co] = wv.y;
            Ws[k4 + 2][co] = wv.z; Ws[k4 + 3][co] = wv.w;
        }
        {
            int kk = k0 + ks;
            int ci = kk / 3;
            int dt = kk - ci * 3 - 1;
#pragma unroll
            for (int j = 0; j < 8; j++) {
                int d = pd[j], h = ph[j], w = pw[j];
                if (cv == 0) h += dt; else if (cv == 1) d += dt; else w += dt;
                unsigned cd = (cv == 0) ? (unsigned)h : ((cv == 1) ? (unsigned)d : (unsigned)w);
                float val = 0.f;
                if (cd < 20u)
                    val = x[((b * CH + ci) * DD + d) * 400 + h * 20 + w];
                Xs[ks][nb + j] = val;
            }
        }
        __syncthreads();
#pragma unroll
        for (int kk = 0; kk < 16; kk++) {
            float4 xr = *reinterpret_cast<const float4*>(&Xs[kk][tn]);
            float wr[8];
#pragma unroll
            for (int i = 0; i < 8; i++) wr[i] = Ws[kk][tc + i];
#pragma unroll
            for (int i = 0; i < 8; i++) {
                acc[i][0] += wr[i] * xr.x; acc[i][1] += wr[i] * xr.y;
                acc[i][2] += wr[i] * xr.z; acc[i][3] += wr[i] * xr.w;
            }
        }
        __syncthreads();
    }
#pragma unroll
    for (int i = 0; i < 8; i++) {
        const int co = tc + i;
        const float bias = Bp[co];
#pragma unroll
        for (int j = 0; j < 4; j++) {
            const int n = n0 + tn + j;
            const __half hv = __float2half_rn(acc[i][j] + bias);
            if (cv == 2) {
                int nl = tn + j;
                int np = permw(nl >> 1) * 2 + (nl & 1);
                g_Vh[((size_t)b * CH + co) * NN + n0 + np] = hv;
            } else {
                int cp = permw(co >> 1) * 2 + (co & 1);
                (cv ? g_Kh : g_Qh)[((size_t)b * NN + n) * CH + cp] = hv;
            }
        }
    }
}

// ---------------------------------------------------------------------------
// Attention kernel: 256 threads, two key-split warp groups, 4-stage ring,
// XOR-swizzled 128B rows, fused exp2 softmax.
// ---------------------------------------------------------------------------
__device__ __forceinline__ uint32_t smem_u32(const void* p) {
    uint32_t a;
    asm("{ .reg .u64 t; cvta.to.shared.u64 t, %1; cvt.u32.u64 %0, t; }" : "=r"(a) : "l"(p));
    return a;
}

#define MMA16(d, a, b0_, b1_)                                                 \
    asm volatile("mma.sync.aligned.m16n8k16.row.col.f32.f16.f16.f32 "         \
                 "{%0,%1,%2,%3},{%4,%5,%6,%7},{%8,%9},{%0,%1,%2,%3};"         \
                 : "+f"((d)[0]), "+f"((d)[1]), "+f"((d)[2]), "+f"((d)[3])     \
                 : "r"((a)[0]), "r"((a)[1]), "r"((a)[2]), "r"((a)[3]),        \
                   "r"(b0_), "r"(b1_))

#define CP16(dst, src)                                                        \
    asm volatile("cp.async.cg.shared.global [%0], [%1], 16;" :: "r"(dst), "l"(src))
#define CP_COMMIT() asm volatile("cp.async.commit_group;" ::: "memory")
#define CP_WAIT1()  asm volatile("cp.async.wait_group 1;" ::: "memory")
#define GBAR(id)    asm volatile("bar.sync %0, 128;" :: "r"(id) : "memory")

__device__ __forceinline__ uint4 lds128(uint32_t a) {
    uint4 v;
    asm volatile("ld.shared.v4.b32 {%0,%1,%2,%3}, [%4];"
                 : "=r"(v.x), "=r"(v.y), "=r"(v.z), "=r"(v.w) : "r"(a));
    return v;
}

__device__ __forceinline__ uint32_t packh(float a, float b) {
    __half2 h = __floats2half2_rn(a, b);
    return *reinterpret_cast<uint32_t*>(&h);
}

__device__ __forceinline__ float ex2(float x) {
    float y;
    asm("ex2.approx.ftz.f32 %0, %1;" : "=f"(y) : "f"(x));
    return y;
}
#define LOG2E 1.4426950408889634f
// exp(s)*2^-18 == ex2(s*log2e - 18); clamp arg so fp16 P <= 2^15.9
#define EXPP(s_) ex2(fminf(fmaf((s_), LOG2E, -18.0f), 15.9f))

// dynamic smem (bytes): K ring[4] @0 (4x8192), V ring[4] @32768, Q @65536 (8192) = 73728
#define KOFF  0
#define VOFF  32768
#define QOFF  65536
// row swizzle: 16B chunk c at row x stored at c ^ f(x&7)
#define FSW(x) ((((x) & 1) << 2) | (((x) & 7) >> 1))

__global__ __launch_bounds__(256, 2) void attn_kernel(float* __restrict__ out)
{
    extern __shared__ __align__(16) uint8_t sm[];
    const int tid = threadIdx.x;
    const int warp = tid >> 5, lane = tid & 31;
    const int g = lane >> 2, r = lane & 3;
    const int gid = tid >> 7;              // key-split warp group 0/1
    const int wg_tid = tid & 127;
    const int wq = warp & 3;               // warp within group
    const int b = blockIdx.y;
    const int m0 = (int)(((unsigned)blockIdx.x * 7936u) / 147u);  // overlap tiles, 1 wave
    const int mw = wq * 16;

    const uint32_t sb = smem_u32(sm);
    // per-lane swizzled chunk offsets for fragment loads (rows with row&7 == g)
    const int fg = FSW(g);
    const uint32_t co0 = (uint32_t)(((((fg >> 2) ^ 0) << 2) | (r ^ (fg & 3))) * 16);
    const uint32_t co1 = (uint32_t)(((((fg >> 2) ^ 1) << 2) | (r ^ (fg & 3))) * 16);

    // staging ids: 128 threads of a group stage one 64-row tile (64B per thread per tensor)
    const int srow = wg_tid >> 1, hb = wg_tid & 1;
    const int fr = FSW(srow);
    const uint32_t kdst = sb + KOFF + srow * 128;
    const uint32_t vdst = sb + VOFF + srow * 128;
    const uint8_t* kg = (const uint8_t*)g_Kh + ((size_t)b * NN + srow) * 128;
    const uint8_t* vg = (const uint8_t*)g_Vh + ((size_t)(b * CH) + srow) * (NN * 2);

    // prologue: each group stages its tiles gid and gid+2 into ring stages (t&3)
#pragma unroll
    for (int sdx = 0; sdx < 2; sdx++) {
        const int tt = gid + 2 * sdx;
        const uint32_t kd = kdst + (tt & 3) * 8192;
        const uint32_t vd = vdst + (tt & 3) * 8192;
        const uint8_t* kgs = kg + (size_t)tt * 8192;
        const uint8_t* vgs = vg + (size_t)tt * 128;
#pragma unroll
        for (int i = 0; i < 4; i++) {
            int c = hb * 4 + i;
            CP16(kd + (uint32_t)((c ^ fr) * 16), kgs + c * 16);
        }
#pragma unroll
        for (int i = 0; i < 4; i++) {
            int c = hb * 4 + i;
            CP16(vd + (uint32_t)((c ^ fr) * 16), vgs + c * 16);
        }
        CP_COMMIT();
    }

    // stage Q tile (64 rows x 128B), all 256 threads
    {
        const int qrow = tid >> 2, qp = tid & 3;
        const int fq = FSW(qrow);
        const uint8_t* qsrc = (const uint8_t*)g_Qh + ((size_t)b * NN + m0 + qrow) * 128;
#pragma unroll
        for (int j2 = 0; j2 < 2; j2++) {
            int j = qp * 2 + j2;
            *reinterpret_cast<uint4*>(sm + QOFF + qrow * 128 + ((j ^ fq) * 16)) =
                *reinterpret_cast<const uint4*>(qsrc + j * 16);
        }
    }
    __syncthreads();

    // persistent Q A-fragments
    uint32_t qa[4][4];
#pragma unroll
    for (int kp = 0; kp < 2; kp++)
#pragma unroll
        for (int h = 0; h < 2; h++) {
            uint4 v = lds128(sb + QOFF + (mw + h * 8 + g) * 128 + (kp ? co1 : co0));
            qa[2 * kp][h]         = v.x;
            qa[2 * kp + 1][h]     = v.y;
            qa[2 * kp][h + 2]     = v.z;
            qa[2 * kp + 1][h + 2] = v.w;
        }

    float oacc[8][4];
#pragma unroll
    for (int i = 0; i < 8; i++)
#pragma unroll
        for (int j = 0; j < 4; j++) oacc[i][j] = 0.f;
    float den0 = 0.f, den1 = 0.f;

#pragma unroll 1
    for (int t = gid; t < 125; t += 2) {
        CP_WAIT1();
        GBAR(gid + 1);                       // group-local: tile t visible to all
        const uint32_t ks = sb + KOFF + (t & 3) * 8192;
        const uint32_t vs = sb + VOFF + (t & 3) * 8192;

        // ---- QK ----
        float s[8][4];
#pragma unroll
        for (int nb = 0; nb < 8; nb++) {
#pragma unroll
            for (int j = 0; j < 4; j++) s[nb][j] = 0.f;
            const uint32_t rb = ks + (nb * 8 + g) * 128;
            uint4 bv0 = lds128(rb + co0);
            MMA16(s[nb], qa[0], bv0.x, bv0.z);
            MMA16(s[nb], qa[1], bv0.y, bv0.w);
            uint4 bv1 = lds128(rb + co1);
            MMA16(s[nb], qa[2], bv1.x, bv1.z);
            MMA16(s[nb], qa[3], bv1.y, bv1.w);
        }

        // ---- softmax numerators; S-frags become PV A-frags (FA2) ----
        uint32_t pa[4][4];
#pragma unroll
        for (int kb = 0; kb < 4; kb++) {
            float e00 = EXPP(s[2 * kb][0]);
            float e01 = EXPP(s[2 * kb][1]);
            float e02 = EXPP(s[2 * kb][2]);
            float e03 = EXPP(s[2 * kb][3]);
            float e10 = EXPP(s[2 * kb + 1][0]);
            float e11 = EXPP(s[2 * kb + 1][1]);
            float e12 = EXPP(s[2 * kb + 1][2]);
            float e13 = EXPP(s[2 * kb + 1][3]);
            den0 += (e00 + e01) + (e10 + e11);
            den1 += (e02 + e03) + (e12 + e13);
            pa[kb][0] = packh(e00, e01);
            pa[kb][1] = packh(e02, e03);
            pa[kb][2] = packh(e10, e11);
            pa[kb][3] = packh(e12, e13);
        }

        // ---- PV ----
#pragma unroll
        for (int cb = 0; cb < 8; cb++) {
            const uint32_t rb = vs + (cb * 8 + g) * 128;
            uint4 bv0 = lds128(rb + co0);
            MMA16(oacc[cb], pa[0], bv0.x, bv0.z);
            MMA16(oacc[cb], pa[1], bv0.y, bv0.w);
            uint4 bv1 = lds128(rb + co1);
            MMA16(oacc[cb], pa[2], bv1.x, bv1.z);
            MMA16(oacc[cb], pa[3], bv1.y, bv1.w);
        }

        GBAR(gid + 1);                       // group done reading stage (t&3)
        if (t + 4 < 125) {
            const int tt = t + 4;
            const uint32_t kd = kdst + (t & 3) * 8192;
            const uint32_t vd = vdst + (t & 3) * 8192;
            const uint8_t* kgs = kg + (size_t)tt * 8192;
            const uint8_t* vgs = vg + (size_t)tt * 128;
#pragma unroll
            for (int i = 0; i < 4; i++) {
                int c = hb * 4 + i;
                CP16(kd + (uint32_t)((c ^ fr) * 16), kgs + c * 16);
            }
#pragma unroll
            for (int i = 0; i < 4; i++) {
                int c = hb * 4 + i;
                CP16(vd + (uint32_t)((c ^ fr) * 16), vgs + c * 16);
            }
        }
        CP_COMMIT();                         // keep wait_group invariant
    }

    // ---- merge group B partials into group A via smem (reuse K ring) ----
    __syncthreads();
    const uint32_t scr = sb + KOFF + (uint32_t)((wq * 32 + lane) * 35 * 4);  // 35-word stride
    if (gid == 1) {
#pragma unroll
        for (int i = 0; i < 8; i++)
#pragma unroll
            for (int j = 0; j < 4; j++)
                asm volatile("st.shared.f32 [%0], %1;" :: "r"(scr + (i * 4 + j) * 4), "f"(oacc[i][j]) : "memory");
        asm volatile("st.shared.f32 [%0], %1;" :: "r"(scr + 32 * 4), "f"(den0) : "memory");
        asm volatile("st.shared.f32 [%0], %1;" :: "r"(scr + 33 * 4), "f"(den1) : "memory");
    }
    __syncthreads();
    if (gid == 0) {
#pragma unroll
        for (int i = 0; i < 8; i++)
#pragma unroll
            for (int j = 0; j < 4; j++) {
                float v;
                asm volatile("ld.shared.f32 %0, [%1];" : "=f"(v) : "r"(scr + (i * 4 + j) * 4));
                oacc[i][j] += v;
            }
        float v0, v1;
        asm volatile("ld.shared.f32 %0, [%1];" : "=f"(v0) : "r"(scr + 32 * 4));
        asm volatile("ld.shared.f32 %0, [%1];" : "=f"(v1) : "r"(scr + 33 * 4));
        den0 += v0; den1 += v1;

        den0 += __shfl_xor_sync(0xffffffffu, den0, 1);
        den0 += __shfl_xor_sync(0xffffffffu, den0, 2);
        den1 += __shfl_xor_sync(0xffffffffu, den1, 1);
        den1 += __shfl_xor_sync(0xffffffffu, den1, 2);
        const float i0 = 1.f / den0, i1 = 1.f / den1;

        const int m = m0 + mw + g;
#pragma unroll
        for (int cb = 0; cb < 8; cb++) {
            int c = cb * 8 + 2 * r;
            out[((size_t)b * CH + c    ) * NN + m]     = oacc[cb][0] * i0;
            out[((size_t)b * CH + c + 1) * NN + m]     = oacc[cb][1] * i0;
            out[((size_t)b * CH + c    ) * NN + m + 8] = oacc[cb][2] * i1;
            out[((size_t)b * CH + c + 1) * NN + m + 8] = oacc[cb][3] * i1;
        }
    }
}

extern "C" void kernel_launch(void* const* d_in, const int* in_sizes, int n_in,
                              void* d_out, int out_size)
{
    const float* x  = (const float*)d_in[0];
    const float* qw = (const float*)d_in[1];
    const float* qb = (const float*)d_in[2];
    const float* kw = (const float*)d_in[3];
    const float* kb = (const float*)d_in[4];
    const float* vw = (const float*)d_in[5];
    const float* vb = (const float*)d_in[6];
    float* out = (float*)d_out;

    cudaFuncSetAttribute(attn_kernel, cudaFuncAttributeMaxDynamicSharedMemorySize, 73728);
    conv_kernel<<<dim3(125, 2, 3), 128>>>(x, qw, qb, kw, kb, vw, vb);
    attn_kernel<<<dim3(148, 2), 256, 73728>>>(out);
}

// round 8
// speedup vs baseline: 2.1589x; 1.0053x over previous
#include <cuda_runtime.h>
#include <cuda_fp16.h>
#include <cstdint>

#define BATCH 2
#define CH    64
#define DD    20
#define NN    8000
#define SK    68

// Projections in fp16. g_Q,g_K: [b][n][c] with channel-words permuted for LDS.128 frags.
// g_V: [b][c][n] with key-words permuted within each 64-block.
__device__ __align__(256) __half g_Qh[BATCH * NN * CH];
__device__ __align__(256) __half g_Kh[BATCH * NN * CH];
__device__ __align__(256) __half g_Vh[BATCH * NN * CH];

// word permutation: natural b32-word w (2 halfs) -> position such that each thread's
// (b0,b1) frag words for a k16-pair are 16B-contiguous (one LDS.128 = B for 2 MMAs)
__device__ __forceinline__ int permw(int w) {
    int k16 = w >> 3, j = w & 7;
    return (k16 >> 1) * 16 + (j & 3) * 4 + ((j >> 2) << 1) + (k16 & 1);
}

// ---------------------------------------------------------------------------
// Conv kernel (unchanged)
// ---------------------------------------------------------------------------
__global__ __launch_bounds__(128) void conv_kernel(
    const float* __restrict__ x,
    const float* __restrict__ qw, const float* __restrict__ qb,
    const float* __restrict__ kw, const float* __restrict__ kbias,
    const float* __restrict__ vw, const float* __restrict__ vb)
{
    const int nt = blockIdx.x, b = blockIdx.y, cv = blockIdx.z;
    const float* Wp = (cv == 0) ? qw : ((cv == 1) ? kw : vw);
    const float* Bp = (cv == 0) ? qb : ((cv == 1) ? kbias : vb);
    const int n0 = nt * 64, tid = threadIdx.x;

    __shared__ float Ws[16][SK];
    __shared__ float Xs[16][SK];

    const int tn = (tid & 15) * 4;
    const int tc = (tid >> 4) * 8;
    float acc[8][4];
#pragma unroll
    for (int i = 0; i < 8; i++)
#pragma unroll
        for (int j = 0; j < 4; j++) acc[i][j] = 0.f;

    const int ks = tid >> 3;
    const int nb = (tid & 7) * 8;
    int pd[8], ph[8], pw[8];
#pragma unroll
    for (int j = 0; j < 8; j++) {
        int n = n0 + nb + j;
        pd[j] = n / 400;
        int rem = n - pd[j] * 400;
        ph[j] = rem / 20;
        pw[j] = rem - ph[j] * 20;
    }

    for (int k0 = 0; k0 < 192; k0 += 16) {
#pragma unroll
        for (int i = 0; i < 2; i++) {
            int idx4 = tid * 2 + i;
            int co = idx4 >> 2, k4 = (idx4 & 3) * 4;
            float4 wv = *reinterpret_cast<const float4*>(Wp + co * 192 + k0 + k4);
            Ws[k4 + 0][co] = wv.x; Ws[k4 + 1][co] = wv.y;
            Ws[k4 + 2][co] = wv.z; Ws[k4 + 3][co] = wv.w;
        }
        {
            int kk = k0 + ks;
            int ci = kk / 3;
            int dt = kk - ci * 3 - 1;
#pragma unroll
            for (int j = 0; j < 8; j++) {
                int d = pd[j], h = ph[j], w = pw[j];
                if (cv == 0) h += dt; else if (cv == 1) d += dt; else w += dt;
                unsigned cd = (cv == 0) ? (unsigned)h : ((cv == 1) ? (unsigned)d : (unsigned)w);
                float val = 0.f;
                if (cd < 20u)
                    val = x[((b * CH + ci) * DD + d) * 400 + h * 20 + w];
                Xs[ks][nb + j] = val;
            }
        }
        __syncthreads();
#pragma unroll
        for (int kk = 0; kk < 16; kk++) {
            float4 xr = *reinterpret_cast<const float4*>(&Xs[kk][tn]);
            float wr[8];
#pragma unroll
            for (int i = 0; i < 8; i++) wr[i] = Ws[kk][tc + i];
#pragma unroll
            for (int i = 0; i < 8; i++) {
                acc[i][0] += wr[i] * xr.x; acc[i][1] += wr[i] * xr.y;
                acc[i][2] += wr[i] * xr.z; acc[i][3] += wr[i] * xr.w;
            }
        }
        __syncthreads();
    }
#pragma unroll
    for (int i = 0; i < 8; i++) {
        const int co = tc + i;
        const float bias = Bp[co];
#pragma unroll
        for (int j = 0; j < 4; j++) {
            const int n = n0 + tn + j;
            const __half hv = __float2half_rn(acc[i][j] + bias);
            if (cv == 2) {
                int nl = tn + j;
                int np = permw(nl >> 1) * 2 + (nl & 1);
                g_Vh[((size_t)b * CH + co) * NN + n0 + np] = hv;
            } else {
                int cp = permw(co >> 1) * 2 + (co & 1);
                (cv ? g_Kh : g_Qh)[((size_t)b * NN + n) * CH + cp] = hv;
            }
        }
    }
}

// ---------------------------------------------------------------------------
// Attention kernel: 256 threads, two key-split groups, 6-stage ring with ONE
// barrier per tile, refill-before-compute, base+imm fragment addressing.
// ---------------------------------------------------------------------------
__device__ __forceinline__ uint32_t smem_u32(const void* p) {
    uint32_t a;
    asm("{ .reg .u64 t; cvta.to.shared.u64 t, %1; cvt.u32.u64 %0, t; }" : "=r"(a) : "l"(p));
    return a;
}

#define MMA16(d, a, b0_, b1_)                                                 \
    asm volatile("mma.sync.aligned.m16n8k16.row.col.f32.f16.f16.f32 "         \
                 "{%0,%1,%2,%3},{%4,%5,%6,%7},{%8,%9},{%0,%1,%2,%3};"         \
                 : "+f"((d)[0]), "+f"((d)[1]), "+f"((d)[2]), "+f"((d)[3])     \
                 : "r"((a)[0]), "r"((a)[1]), "r"((a)[2]), "r"((a)[3]),        \
                   "r"(b0_), "r"(b1_))

#define CP16(dst, src)                                                        \
    asm volatile("cp.async.cg.shared.global [%0], [%1], 16;" :: "r"(dst), "l"(src))
#define CP_COMMIT() asm volatile("cp.async.commit_group;" ::: "memory")
#define CP_WAIT1()  asm volatile("cp.async.wait_group 1;" ::: "memory")
#define GBAR(id)    asm volatile("bar.sync %0, 128;" :: "r"(id) : "memory")

__device__ __forceinline__ uint4 lds128(uint32_t a) {
    uint4 v;
    asm volatile("ld.shared.v4.b32 {%0,%1,%2,%3}, [%4];"
                 : "=r"(v.x), "=r"(v.y), "=r"(v.z), "=r"(v.w) : "r"(a));
    return v;
}

__device__ __forceinline__ uint32_t packh(float a, float b) {
    __half2 h = __floats2half2_rn(a, b);
    return *reinterpret_cast<uint32_t*>(&h);
}

__device__ __forceinline__ float ex2(float x) {
    float y;
    asm("ex2.approx.ftz.f32 %0, %1;" : "=f"(y) : "f"(x));
    return y;
}
#define LOG2E 1.4426950408889634f
// exp(s)*2^-18 == ex2(s*log2e - 18); clamp arg so fp16 P <= 2^15.9
#define EXPP(s_) ex2(fminf(fmaf((s_), LOG2E, -18.0f), 15.9f))

// dynamic smem (bytes): K ring[6] @0 (6x8192=49152), V ring[6] @49152, Q @98304 = 106496
#define KOFF  0
#define VOFF  49152
#define QOFF  98304
#define SMEMSZ 106496
// row swizzle: 16B chunk c at row x stored at c ^ f(x&7)
#define FSW(x) ((((x) & 1) << 2) | (((x) & 7) >> 1))

__global__ __launch_bounds__(256, 2) void attn_kernel(float* __restrict__ out)
{
    extern __shared__ __align__(16) uint8_t sm[];
    const int tid = threadIdx.x;
    const int warp = tid >> 5, lane = tid & 31;
    const int g = lane >> 2, r = lane & 3;
    const int gid = tid >> 7;              // key-split warp group 0/1
    const int wg_tid = tid & 127;
    const int wq = warp & 3;               // warp within group
    const int b = blockIdx.y;
    const int m0 = (int)(((unsigned)blockIdx.x * 7936u) / 147u);  // overlap tiles, 1 wave
    const int mw = wq * 16;

    const uint32_t sb = smem_u32(sm);
    // per-lane swizzled chunk offsets for fragment loads (rows with row&7 == g)
    const int fg = FSW(g);
    const uint32_t co0 = (uint32_t)(((((fg >> 2) ^ 0) << 2) | (r ^ (fg & 3))) * 16);
    const uint32_t co1 = (uint32_t)(((((fg >> 2) ^ 1) << 2) | (r ^ (fg & 3))) * 16);
    const uint32_t gco = (uint32_t)(g * 128);

    // staging ids: 128 threads of a group stage one 64-row tile (64B per thread per tensor)
    const int srow = wg_tid >> 1, hb = wg_tid & 1;
    const int fr = FSW(srow);
    const uint32_t kdst = sb + KOFF + srow * 128;
    const uint32_t vdst = sb + VOFF + srow * 128;
    const uint8_t* kg = (const uint8_t*)g_Kh + ((size_t)b * NN + srow) * 128;
    const uint8_t* vg = (const uint8_t*)g_Vh + ((size_t)(b * CH) + srow) * (NN * 2);

    // prologue: each group stages tiles gid (stage gid) and gid+2 (stage gid+2)
#pragma unroll
    for (int sdx = 0; sdx < 2; sdx++) {
        const int tt = gid + 2 * sdx;
        const uint32_t kd = kdst + tt * 8192;     // stage == tile index here
        const uint32_t vd = vdst + tt * 8192;
        const uint8_t* kgs = kg + (size_t)tt * 8192;
        const uint8_t* vgs = vg + (size_t)tt * 128;
#pragma unroll
        for (int i = 0; i < 4; i++) {
            int c = hb * 4 + i;
            CP16(kd + (uint32_t)((c ^ fr) * 16), kgs + c * 16);
        }
#pragma unroll
        for (int i = 0; i < 4; i++) {
            int c = hb * 4 + i;
            CP16(vd + (uint32_t)((c ^ fr) * 16), vgs + c * 16);
        }
        CP_COMMIT();
    }

    // stage Q tile (64 rows x 128B), all 256 threads
    {
        const int qrow = tid >> 2, qp = tid & 3;
        const int fq = FSW(qrow);
        const uint8_t* qsrc = (const uint8_t*)g_Qh + ((size_t)b * NN + m0 + qrow) * 128;
#pragma unroll
        for (int j2 = 0; j2 < 2; j2++) {
            int j = qp * 2 + j2;
            *reinterpret_cast<uint4*>(sm + QOFF + qrow * 128 + ((j ^ fq) * 16)) =
                *reinterpret_cast<const uint4*>(qsrc + j * 16);
        }
    }
    __syncthreads();

    // persistent Q A-fragments
    uint32_t qa[4][4];
#pragma unroll
    for (int kp = 0; kp < 2; kp++)
#pragma unroll
        for (int h = 0; h < 2; h++) {
            uint4 v = lds128(sb + QOFF + (mw + h * 8 + g) * 128 + (kp ? co1 : co0));
            qa[2 * kp][h]         = v.x;
            qa[2 * kp + 1][h]     = v.y;
            qa[2 * kp][h + 2]     = v.z;
            qa[2 * kp + 1][h + 2] = v.w;
        }

    float oacc[8][4];
#pragma unroll
    for (int i = 0; i < 8; i++)
#pragma unroll
        for (int j = 0; j < 4; j++) oacc[i][j] = 0.f;
    float den0 = 0.f, den1 = 0.f;

    int st = gid;                            // stage of current tile (tile mod 6)
#pragma unroll 1
    for (int t = gid; t < 125; t += 2) {
        CP_WAIT1();
        GBAR(gid + 1);   // tile t data visible to group; all warps done reading stage st+4's old tile

        // ---- refill stage (st+4) mod 6 with tile t+4 (overlaps compute below) ----
        {
            int pst = st + 4; if (pst >= 6) pst -= 6;
            if (t + 4 < 125) {
                const int tt = t + 4;
                const uint32_t kd = kdst + pst * 8192;
                const uint32_t vd = vdst + pst * 8192;
                const uint8_t* kgs = kg + (size_t)tt * 8192;
                const uint8_t* vgs = vg + (size_t)tt * 128;
#pragma unroll
                for (int i = 0; i < 4; i++) {
                    int c = hb * 4 + i;
                    CP16(kd + (uint32_t)((c ^ fr) * 16), kgs + c * 16);
                }
#pragma unroll
                for (int i = 0; i < 4; i++) {
                    int c = hb * 4 + i;
                    CP16(vd + (uint32_t)((c ^ fr) * 16), vgs + c * 16);
                }
            }
            CP_COMMIT();
        }

        // ---- per-tile fragment base addresses (inner loads are base + imm) ----
        const uint32_t ksg = sb + KOFF + st * 8192 + gco;
        const uint32_t vsg = sb + VOFF + st * 8192 + gco;
        const uint32_t kb0 = ksg + co0, kb1 = ksg + co1;
        const uint32_t vb0 = vsg + co0, vb1 = vsg + co1;

        // ---- QK ----
        float s[8][4];
#pragma unroll
        for (int nb = 0; nb < 8; nb++) {
#pragma unroll
            for (int j = 0; j < 4; j++) s[nb][j] = 0.f;
            uint4 bv0 = lds128(kb0 + nb * 1024);
            MMA16(s[nb], qa[0], bv0.x, bv0.z);
            MMA16(s[nb], qa[1], bv0.y, bv0.w);
            uint4 bv1 = lds128(kb1 + nb * 1024);
            MMA16(s[nb], qa[2], bv1.x, bv1.z);
            MMA16(s[nb], qa[3], bv1.y, bv1.w);
        }

        // ---- softmax numerators; S-frags become PV A-frags (FA2) ----
        uint32_t pa[4][4];
#pragma unroll
        for (int kb = 0; kb < 4; kb++) {
            float e00 = EXPP(s[2 * kb][0]);
            float e01 = EXPP(s[2 * kb][1]);
            float e02 = EXPP(s[2 * kb][2]);
            float e03 = EXPP(s[2 * kb][3]);
            float e10 = EXPP(s[2 * kb + 1][0]);
            float e11 = EXPP(s[2 * kb + 1][1]);
            float e12 = EXPP(s[2 * kb + 1][2]);
            float e13 = EXPP(s[2 * kb + 1][3]);
            den0 += (e00 + e01) + (e10 + e11);
            den1 += (e02 + e03) + (e12 + e13);
            pa[kb][0] = packh(e00, e01);
            pa[kb][1] = packh(e02, e03);
            pa[kb][2] = packh(e10, e11);
            pa[kb][3] = packh(e12, e13);
        }

        // ---- PV ----
#pragma unroll
        for (int cb = 0; cb < 8; cb++) {
            uint4 bv0 = lds128(vb0 + cb * 1024);
            MMA16(oacc[cb], pa[0], bv0.x, bv0.z);
            MMA16(oacc[cb], pa[1], bv0.y, bv0.w);
            uint4 bv1 = lds128(vb1 + cb * 1024);
            MMA16(oacc[cb], pa[2], bv1.x, bv1.z);
            MMA16(oacc[cb], pa[3], bv1.y, bv1.w);
        }

        st += 2; if (st >= 6) st -= 6;
    }

    // ---- merge group B partials into group A via smem (reuse K ring) ----
    __syncthreads();
    const uint32_t scr = sb + KOFF + (uint32_t)((wq * 32 + lane) * 35 * 4);  // 35-word stride
    if (gid == 1) {
#pragma unroll
        for (int i = 0; i < 8; i++)
#pragma unroll
            for (int j = 0; j < 4; j++)
                asm volatile("st.shared.f32 [%0], %1;" :: "r"(scr + (i * 4 + j) * 4), "f"(oacc[i][j]) : "memory");
        asm volatile("st.shared.f32 [%0], %1;" :: "r"(scr + 32 * 4), "f"(den0) : "memory");
        asm volatile("st.shared.f32 [%0], %1;" :: "r"(scr + 33 * 4), "f"(den1) : "memory");
    }
    __syncthreads();
    if (gid == 0) {
#pragma unroll
        for (int i = 0; i < 8; i++)
#pragma unroll
            for (int j = 0; j < 4; j++) {
                float v;
                asm volatile("ld.shared.f32 %0, [%1];" : "=f"(v) : "r"(scr + (i * 4 + j) * 4));
                oacc[i][j] += v;
            }
        float v0, v1;
        asm volatile("ld.shared.f32 %0, [%1];" : "=f"(v0) : "r"(scr + 32 * 4));
        asm volatile("ld.shared.f32 %0, [%1];" : "=f"(v1) : "r"(scr + 33 * 4));
        den0 += v0; den1 += v1;

        den0 += __shfl_xor_sync(0xffffffffu, den0, 1);
        den0 += __shfl_xor_sync(0xffffffffu, den0, 2);
        den1 += __shfl_xor_sync(0xffffffffu, den1, 1);
        den1 += __shfl_xor_sync(0xffffffffu, den1, 2);
        const float i0 = 1.f / den0, i1 = 1.f / den1;

        const int m = m0 + mw + g;
#pragma unroll
        for (int cb = 0; cb < 8; cb++) {
            int c = cb * 8 + 2 * r;
            out[((size_t)b * CH + c    ) * NN + m]     = oacc[cb][0] * i0;
            out[((size_t)b * CH + c + 1) * NN + m]     = oacc[cb][1] * i0;
            out[((size_t)b * CH + c    ) * NN + m + 8] = oacc[cb][2] * i1;
            out[((size_t)b * CH + c + 1) * NN + m + 8] = oacc[cb][3] * i1;
        }
    }
}

extern "C" void kernel_launch(void* const* d_in, const int* in_sizes, int n_in,
                              void* d_out, int out_size)
{
    const float* x  = (const float*)d_in[0];
    const float* qw = (const float*)d_in[1];
    const float* qb = (const float*)d_in[2];
    const float* kw = (const float*)d_in[3];
    const float* kb = (const float*)d_in[4];
    const float* vw = (const float*)d_in[5];
    const float* vb = (const float*)d_in[6];
    float* out = (float*)d_out;

    cudaFuncSetAttribute(attn_kernel, cudaFuncAttributeMaxDynamicSharedMemorySize, SMEMSZ);
    conv_kernel<<<dim3(125, 2, 3), 128>>>(x, qw, qb, kw, kb, vw, vb);
    attn_kernel<<<dim3(148, 2), 256, SMEMSZ>>>(out);
}

// round 10
// speedup vs baseline: 2.1806x; 1.0101x over previous
#include <cuda_runtime.h>
#include <cuda_fp16.h>
#include <cstdint>

#define BATCH 2
#define CH    64
#define DD    20
#define NN    8000
#define SK    68

// Projections in fp16. g_Q,g_K: [b][n][c] with channel-words permuted for LDS.128 frags.
// g_V: [b][c][n] with key-words permuted within each 64-block.
__device__ __align__(256) __half g_Qh[BATCH * NN * CH];
__device__ __align__(256) __half g_Kh[BATCH * NN * CH];
__device__ __align__(256) __half g_Vh[BATCH * NN * CH];

// word permutation: natural b32-word w (2 halfs) -> position such that each thread's
// (b0,b1) frag words for a k16-pair are 16B-contiguous (one LDS.128 = B for 2 MMAs)
__device__ __forceinline__ int permw(int w) {
    int k16 = w >> 3, j = w & 7;
    return (k16 >> 1) * 16 + (j & 3) * 4 + ((j >> 2) << 1) + (k16 & 1);
}

#define FMA2(d, a, b_) \
    asm("fma.rn.f32x2 %0, %1, %2, %0;" : "+l"(d) : "l"(a), "l"(b_))

// ---------------------------------------------------------------------------
// Conv kernel: GEMM-style, inner loop on packed f32x2 FMA (channel pairs).
// ---------------------------------------------------------------------------
__global__ __launch_bounds__(128) void conv_kernel(
    const float* __restrict__ x,
    const float* __restrict__ qw, const float* __restrict__ qb,
    const float* __restrict__ kw, const float* __restrict__ kbias,
    const float* __restrict__ vw, const float* __restrict__ vb)
{
    const int nt = blockIdx.x, b = blockIdx.y, cv = blockIdx.z;
    const float* Wp = (cv == 0) ? qw : ((cv == 1) ? kw : vw);
    const float* Bp = (cv == 0) ? qb : ((cv == 1) ? kbias : vb);
    const int n0 = nt * 64, tid = threadIdx.x;

    __shared__ float Ws[16][SK];
    __shared__ float Xs[16][SK];

    const int tn = (tid & 15) * 4;   // 4 n columns (16B aligned)
    const int tc = (tid >> 4) * 8;   // 8 output channels = 4 pairs

    uint64_t acc2[4][4];             // [channel pair][n col], f32x2 lanes (lo=even co)
#pragma unroll
    for (int ip = 0; ip < 4; ip++)
#pragma unroll
        for (int j = 0; j < 4; j++) acc2[ip][j] = 0ull;

    const int ks = tid >> 3;
    const int nb = (tid & 7) * 8;
    int pd[8], ph[8], pw[8];
#pragma unroll
    for (int j = 0; j < 8; j++) {
        int n = n0 + nb + j;
        pd[j] = n / 400;
        int rem = n - pd[j] * 400;
        ph[j] = rem / 20;
        pw[j] = rem - ph[j] * 20;
    }

    for (int k0 = 0; k0 < 192; k0 += 16) {
#pragma unroll
        for (int i = 0; i < 2; i++) {
            int idx4 = tid * 2 + i;
            int co = idx4 >> 2, k4 = (idx4 & 3) * 4;
            float4 wv = *reinterpret_cast<const float4*>(Wp + co * 192 + k0 + k4);
            Ws[k4 + 0][co] = wv.x; Ws[k4 + 1][co] = wv.y;
            Ws[k4 + 2][co] = wv.z; Ws[k4 + 3][co] = wv.w;
        }
        {
            int kk = k0 + ks;
            int ci = kk / 3;
            int dt = kk - ci * 3 - 1;
#pragma unroll
            for (int j = 0; j < 8; j++) {
                int d = pd[j], h = ph[j], w = pw[j];
                if (cv == 0) h += dt; else if (cv == 1) d += dt; else w += dt;
                unsigned cd = (cv == 0) ? (unsigned)h : ((cv == 1) ? (unsigned)d : (unsigned)w);
                float val = 0.f;
                if (cd < 20u)
                    val = x[((b * CH + ci) * DD + d) * 400 + h * 20 + w];
                Xs[ks][nb + j] = val;
            }
        }
        __syncthreads();
#pragma unroll
        for (int kk = 0; kk < 16; kk++) {
            float4 xr = *reinterpret_cast<const float4*>(&Xs[kk][tn]);
            const uint64_t* wp = reinterpret_cast<const uint64_t*>(&Ws[kk][tc]);
            uint64_t w2[4];
            w2[0] = wp[0]; w2[1] = wp[1]; w2[2] = wp[2]; w2[3] = wp[3];
            uint64_t xb[4];
            asm("mov.b64 %0, {%1,%1};" : "=l"(xb[0]) : "f"(xr.x));
            asm("mov.b64 %0, {%1,%1};" : "=l"(xb[1]) : "f"(xr.y));
            asm("mov.b64 %0, {%1,%1};" : "=l"(xb[2]) : "f"(xr.z));
            asm("mov.b64 %0, {%1,%1};" : "=l"(xb[3]) : "f"(xr.w));
#pragma unroll
            for (int ip = 0; ip < 4; ip++) {
                FMA2(acc2[ip][0], w2[ip], xb[0]);
                FMA2(acc2[ip][1], w2[ip], xb[1]);
                FMA2(acc2[ip][2], w2[ip], xb[2]);
                FMA2(acc2[ip][3], w2[ip], xb[3]);
            }
        }
        __syncthreads();
    }
#pragma unroll
    for (int ip = 0; ip < 4; ip++) {
        float lo[4], hi[4];
#pragma unroll
        for (int j = 0; j < 4; j++)
            asm("mov.b64 {%0,%1}, %2;" : "=f"(lo[j]), "=f"(hi[j]) : "l"(acc2[ip][j]));
#pragma unroll
        for (int half = 0; half < 2; half++) {
            const int co = tc + 2 * ip + half;
            const float bias = Bp[co];
#pragma unroll
            for (int j = 0; j < 4; j++) {
                const int n = n0 + tn + j;
                const float v = (half ? hi[j] : lo[j]) + bias;
                const __half hv = __float2half_rn(v);
                if (cv == 2) {
                    int nl = tn + j;
                    int np = permw(nl >> 1) * 2 + (nl & 1);
                    g_Vh[((size_t)b * CH + co) * NN + n0 + np] = hv;
                } else {
                    int cp = permw(co >> 1) * 2 + (co & 1);
                    (cv ? g_Kh : g_Qh)[((size_t)b * NN + n) * CH + cp] = hv;
                }
            }
        }
    }
}

// ---------------------------------------------------------------------------
// Attention kernel: 256 threads, two key-split groups, 6-stage ring, one
// barrier per tile, den via ones-MMA, satfinite softmax pack.
// ---------------------------------------------------------------------------
__device__ __forceinline__ uint32_t smem_u32(const void* p) {
    uint32_t a;
    asm("{ .reg .u64 t; cvta.to.shared.u64 t, %1; cvt.u32.u64 %0, t; }" : "=r"(a) : "l"(p));
    return a;
}

#define MMA16(d, a, b0_, b1_)                                                 \
    asm volatile("mma.sync.aligned.m16n8k16.row.col.f32.f16.f16.f32 "         \
                 "{%0,%1,%2,%3},{%4,%5,%6,%7},{%8,%9},{%0,%1,%2,%3};"         \
                 : "+f"((d)[0]), "+f"((d)[1]), "+f"((d)[2]), "+f"((d)[3])     \
                 : "r"((a)[0]), "r"((a)[1]), "r"((a)[2]), "r"((a)[3]),        \
                   "r"(b0_), "r"(b1_))

#define CP16(dst, src)                                                        \
    asm volatile("cp.async.cg.shared.global [%0], [%1], 16;" :: "r"(dst), "l"(src))
#define CP_COMMIT() asm volatile("cp.async.commit_group;" ::: "memory")
#define CP_WAIT1()  asm volatile("cp.async.wait_group 1;" ::: "memory")
#define GBAR(id)    asm volatile("bar.sync %0, 128;" :: "r"(id) : "memory")

__device__ __forceinline__ uint4 lds128(uint32_t a) {
    uint4 v;
    asm volatile("ld.shared.v4.b32 {%0,%1,%2,%3}, [%4];"
                 : "=r"(v.x), "=r"(v.y), "=r"(v.z), "=r"(v.w) : "r"(a));
    return v;
}

__device__ __forceinline__ float ex2(float x) {
    float y;
    asm("ex2.approx.ftz.f32 %0, %1;" : "=f"(y) : "f"(x));
    return y;
}
#define LOG2E 1.4426950408889634f
// pack (lo,hi) f32 -> f16x2 with saturate-to-finite (clamps P at half max)
#define CVTPK(d, hi_, lo_)                                                    \
    asm("cvt.rn.satfinite.f16x2.f32 %0, %1, %2;" : "=r"(d) : "f"(hi_), "f"(lo_))

// dynamic smem (bytes): K ring[6] @0 (6x8192=49152), V ring[6] @49152, Q @98304 = 106496
#define KOFF  0
#define VOFF  49152
#define QOFF  98304
#define SMEMSZ 106496
// row swizzle: 16B chunk c at row x stored at c ^ f(x&7)
#define FSW(x) ((((x) & 1) << 2) | (((x) & 7) >> 1))

__global__ __launch_bounds__(256, 2) void attn_kernel(float* __restrict__ out)
{
    extern __shared__ __align__(16) uint8_t sm[];
    const int tid = threadIdx.x;
    const int warp = tid >> 5, lane = tid & 31;
    const int g = lane >> 2, r = lane & 3;
    const int gid = tid >> 7;              // key-split warp group 0/1
    const int wg_tid = tid & 127;
    const int wq = warp & 3;               // warp within group
    const int b = blockIdx.y;
    const int m0 = (int)(((unsigned)blockIdx.x * 7936u) / 147u);  // overlap tiles, 1 wave
    const int mw = wq * 16;

    const uint32_t sb = smem_u32(sm);
    // per-lane swizzled chunk offsets for fragment loads (rows with row&7 == g)
    const int fg = FSW(g);
    const uint32_t co0 = (uint32_t)(((((fg >> 2) ^ 0) << 2) | (r ^ (fg & 3))) * 16);
    const uint32_t co1 = (uint32_t)(((((fg >> 2) ^ 1) << 2) | (r ^ (fg & 3))) * 16);
    const uint32_t gco = (uint32_t)(g * 128);

    // staging ids: 128 threads of a group stage one 64-row tile (64B per thread per tensor)
    const int srow = wg_tid >> 1, hb = wg_tid & 1;
    const int fr = FSW(srow);
    const uint32_t kdst = sb + KOFF + srow * 128;
    const uint32_t vdst = sb + VOFF + srow * 128;
    const uint8_t* kg = (const uint8_t*)g_Kh + ((size_t)b * NN + srow) * 128;
    const uint8_t* vg = (const uint8_t*)g_Vh + ((size_t)(b * CH) + srow) * (NN * 2);

    // prologue: each group stages tiles gid (stage gid) and gid+2 (stage gid+2)
#pragma unroll
    for (int sdx = 0; sdx < 2; sdx++) {
        const int tt = gid + 2 * sdx;
        const uint32_t kd = kdst + tt * 8192;
        const uint32_t vd = vdst + tt * 8192;
        const uint8_t* kgs = kg + (size_t)tt * 8192;
        const uint8_t* vgs = vg + (size_t)tt * 128;
#pragma unroll
        for (int i = 0; i < 4; i++) {
            int c = hb * 4 + i;
            CP16(kd + (uint32_t)((c ^ fr) * 16), kgs + c * 16);
        }
#pragma unroll
        for (int i = 0; i < 4; i++) {
            int c = hb * 4 + i;
            CP16(vd + (uint32_t)((c ^ fr) * 16), vgs + c * 16);
        }
        CP_COMMIT();
    }

    // stage Q tile (64 rows x 128B), all 256 threads
    {
        const int qrow = tid >> 2, qp = tid & 3;
        const int fq = FSW(qrow);
        const uint8_t* qsrc = (const uint8_t*)g_Qh + ((size_t)b * NN + m0 + qrow) * 128;
#pragma unroll
        for (int j2 = 0; j2 < 2; j2++) {
            int j = qp * 2 + j2;
            *reinterpret_cast<uint4*>(sm + QOFF + qrow * 128 + ((j ^ fq) * 16)) =
                *reinterpret_cast<const uint4*>(qsrc + j * 16);
        }
    }
    __syncthreads();

    // persistent Q A-fragments
    uint32_t qa[4][4];
#pragma unroll
    for (int kp = 0; kp < 2; kp++)
#pragma unroll
        for (int h = 0; h < 2; h++) {
            uint4 v = lds128(sb + QOFF + (mw + h * 8 + g) * 128 + (kp ? co1 : co0));
            qa[2 * kp][h]         = v.x;
            qa[2 * kp + 1][h]     = v.y;
            qa[2 * kp][h + 2]     = v.z;
            qa[2 * kp + 1][h + 2] = v.w;
        }

    float oacc[8][4];
#pragma unroll
    for (int i = 0; i < 8; i++)
#pragma unroll
        for (int j = 0; j < 4; j++) oacc[i][j] = 0.f;
    float dacc[4] = {0.f, 0.f, 0.f, 0.f};     // row-sum accumulator (den) via ones-MMA
    const uint32_t bones = 0x3C003C00u;       // half2(1.0, 1.0)

    int st = gid;                            // stage of current tile (tile mod 6)
#pragma unroll 1
    for (int t = gid; t < 125; t += 2) {
        CP_WAIT1();
        GBAR(gid + 1);   // tile t data visible to group; stage st+4's old tile fully read

        // ---- refill stage (st+4) mod 6 with tile t+4 (overlaps compute below) ----
        {
            int pst = st + 4; if (pst >= 6) pst -= 6;
            if (t + 4 < 125) {
                const int tt = t + 4;
                const uint32_t kd = kdst + pst * 8192;
                const uint32_t vd = vdst + pst * 8192;
                const uint8_t* kgs = kg + (size_t)tt * 8192;
                const uint8_t* vgs = vg + (size_t)tt * 128;
#pragma unroll
                for (int i = 0; i < 4; i++) {
                    int c = hb * 4 + i;
                    CP16(kd + (uint32_t)((c ^ fr) * 16), kgs + c * 16);
                }
#pragma unroll
                for (int i = 0; i < 4; i++) {
                    int c = hb * 4 + i;
                    CP16(vd + (uint32_t)((c ^ fr) * 16), vgs + c * 16);
                }
            }
            CP_COMMIT();
        }

        // ---- per-tile fragment base addresses (inner loads are base + imm) ----
        const uint32_t ksg = sb + KOFF + st * 8192 + gco;
        const uint32_t vsg = sb + VOFF + st * 8192 + gco;
        const uint32_t kb0 = ksg + co0, kb1 = ksg + co1;
        const uint32_t vb0 = vsg + co0, vb1 = vsg + co1;

        // ---- QK ----
        float s[8][4];
#pragma unroll
        for (int nb = 0; nb < 8; nb++) {
#pragma unroll
            for (int j = 0; j < 4; j++) s[nb][j] = 0.f;
            uint4 bv0 = lds128(kb0 + nb * 1024);
            MMA16(s[nb], qa[0], bv0.x, bv0.z);
            MMA16(s[nb], qa[1], bv0.y, bv0.w);
            uint4 bv1 = lds128(kb1 + nb * 1024);
            MMA16(s[nb], qa[2], bv1.x, bv1.z);
            MMA16(s[nb], qa[3], bv1.y, bv1.w);
        }

        // ---- softmax numerators: exp2(s*log2e - 18), satfinite pack to half2 ----
        uint32_t pa[4][4];
#pragma unroll
        for (int kb = 0; kb < 4; kb++) {
            float e00 = ex2(fmaf(s[2 * kb][0], LOG2E, -18.f));
            float e01 = ex2(fmaf(s[2 * kb][1], LOG2E, -18.f));
            float e02 = ex2(fmaf(s[2 * kb][2], LOG2E, -18.f));
            float e03 = ex2(fmaf(s[2 * kb][3], LOG2E, -18.f));
            float e10 = ex2(fmaf(s[2 * kb + 1][0], LOG2E, -18.f));
            float e11 = ex2(fmaf(s[2 * kb + 1][1], LOG2E, -18.f));
            float e12 = ex2(fmaf(s[2 * kb + 1][2], LOG2E, -18.f));
            float e13 = ex2(fmaf(s[2 * kb + 1][3], LOG2E, -18.f));
            CVTPK(pa[kb][0], e01, e00);   // lo=e00, hi=e01 (row g,   k-lo)
            CVTPK(pa[kb][1], e03, e02);   // row g+8, k-lo
            CVTPK(pa[kb][2], e11, e10);   // row g,   k-hi
            CVTPK(pa[kb][3], e13, e12);   // row g+8, k-hi
        }

        // ---- den: row-sum of P via ones-B MMA (fp32 tensor accumulate) ----
#pragma unroll
        for (int kb = 0; kb < 4; kb++)
            MMA16(dacc, pa[kb], bones, bones);

        // ---- PV ----
#pragma unroll
        for (int cb = 0; cb < 8; cb++) {
            uint4 bv0 = lds128(vb0 + cb * 1024);
            MMA16(oacc[cb], pa[0], bv0.x, bv0.z);
            MMA16(oacc[cb], pa[1], bv0.y, bv0.w);
            uint4 bv1 = lds128(vb1 + cb * 1024);
            MMA16(oacc[cb], pa[2], bv1.x, bv1.z);
            MMA16(oacc[cb], pa[3], bv1.y, bv1.w);
        }

        st += 2; if (st >= 6) st -= 6;
    }

    float den0 = dacc[0], den1 = dacc[2];    // full row sums (rows g, g+8)

    // ---- merge group B partials into group A via smem (reuse K ring) ----
    __syncthreads();
    const uint32_t scr = sb + KOFF + (uint32_t)((wq * 32 + lane) * 35 * 4);  // 35-word stride
    if (gid == 1) {
#pragma unroll
        for (int i = 0; i < 8; i++)
#pragma unroll
            for (int j = 0; j < 4; j++)
                asm volatile("st.shared.f32 [%0], %1;" :: "r"(scr + (i * 4 + j) * 4), "f"(oacc[i][j]) : "memory");
        asm volatile("st.shared.f32 [%0], %1;" :: "r"(scr + 32 * 4), "f"(den0) : "memory");
        asm volatile("st.shared.f32 [%0], %1;" :: "r"(scr + 33 * 4), "f"(den1) : "memory");
    }
    __syncthreads();
    if (gid == 0) {
#pragma unroll
        for (int i = 0; i < 8; i++)
#pragma unroll
            for (int j = 0; j < 4; j++) {
                float v;
                asm volatile("ld.shared.f32 %0, [%1];" : "=f"(v) : "r"(scr + (i * 4 + j) * 4));
                oacc[i][j] += v;
            }
        float v0, v1;
        asm volatile("ld.shared.f32 %0, [%1];" : "=f"(v0) : "r"(scr + 32 * 4));
        asm volatile("ld.shared.f32 %0, [%1];" : "=f"(v1) : "r"(scr + 33 * 4));
        den0 += v0; den1 += v1;

        const float i0 = 1.f / den0, i1 = 1.f / den1;

        const int m = m0 + mw + g;
#pragma unroll
        for (int cb = 0; cb < 8; cb++) {
            int c = cb * 8 + 2 * r;
            out[((size_t)b * CH + c    ) * NN + m]     = oacc[cb][0] * i0;
            out[((size_t)b * CH + c + 1) * NN + m]     = oacc[cb][1] * i0;
            out[((size_t)b * CH + c    ) * NN + m + 8] = oacc[cb][2] * i1;
            out[((size_t)b * CH + c + 1) * NN + m + 8] = oacc[cb][3] * i1;
        }
    }
}

extern "C" void kernel_launch(void* const* d_in, const int* in_sizes, int n_in,
                              void* d_out, int out_size)
{
    const float* x  = (const float*)d_in[0];
    const float* qw = (const float*)d_in[1];
    const float* qb = (const float*)d_in[2];
    const float* kw = (const float*)d_in[3];
    const float* kb = (const float*)d_in[4];
    const float* vw = (const float*)d_in[5];
    const float* vb = (const float*)d_in[6];
    float* out = (float*)d_out;

    cudaFuncSetAttribute(attn_kernel, cudaFuncAttributeMaxDynamicSharedMemorySize, SMEMSZ);
    conv_kernel<<<dim3(125, 2, 3), 128>>>(x, qw, qb, kw, kb, vw, vb);
    attn_kernel<<<dim3(148, 2), 256, SMEMSZ>>>(out);
}

// round 11
// speedup vs baseline: 2.2189x; 1.0176x over previous
#include <cuda_runtime.h>
#include <cuda_fp16.h>
#include <cstdint>

#define BATCH 2
#define CH    64
#define DD    20
#define NN    8000
#define SK    68

// Projections in fp16. g_Q,g_K: [b][n][c] with channel-words permuted for LDS.128 frags.
// g_V: [b][c][n] with key-words permuted within each 64-block.
__device__ __align__(256) __half g_Qh[BATCH * NN * CH];
__device__ __align__(256) __half g_Kh[BATCH * NN * CH];
__device__ __align__(256) __half g_Vh[BATCH * NN * CH];

// word permutation: natural b32-word w (2 halfs) -> position such that each thread's
// (b0,b1) frag words for a k16-pair are 16B-contiguous (one LDS.128 = B for 2 MMAs)
__device__ __forceinline__ int permw(int w) {
    int k16 = w >> 3, j = w & 7;
    return (k16 >> 1) * 16 + (j & 3) * 4 + ((j >> 2) << 1) + (k16 & 1);
}

#define FMA2(d, a, b_) \
    asm("fma.rn.f32x2 %0, %1, %2, %0;" : "+l"(d) : "l"(a), "l"(b_))

// ---------------------------------------------------------------------------
// Conv kernel: GEMM-style, inner loop on packed f32x2 FMA (channel pairs).
// ---------------------------------------------------------------------------
__global__ __launch_bounds__(128) void conv_kernel(
    const float* __restrict__ x,
    const float* __restrict__ qw, const float* __restrict__ qb,
    const float* __restrict__ kw, const float* __restrict__ kbias,
    const float* __restrict__ vw, const float* __restrict__ vb)
{
    const int nt = blockIdx.x, b = blockIdx.y, cv = blockIdx.z;
    const float* Wp = (cv == 0) ? qw : ((cv == 1) ? kw : vw);
    const float* Bp = (cv == 0) ? qb : ((cv == 1) ? kbias : vb);
    const int n0 = nt * 64, tid = threadIdx.x;

    __shared__ float Ws[16][SK];
    __shared__ float Xs[16][SK];

    const int tn = (tid & 15) * 4;   // 4 n columns (16B aligned)
    const int tc = (tid >> 4) * 8;   // 8 output channels = 4 pairs

    uint64_t acc2[4][4];             // [channel pair][n col], f32x2 lanes (lo=even co)
#pragma unroll
    for (int ip = 0; ip < 4; ip++)
#pragma unroll
        for (int j = 0; j < 4; j++) acc2[ip][j] = 0ull;

    const int ks = tid >> 3;
    const int nb = (tid & 7) * 8;
    int pd[8], ph[8], pw[8];
#pragma unroll
    for (int j = 0; j < 8; j++) {
        int n = n0 + nb + j;
        pd[j] = n / 400;
        int rem = n - pd[j] * 400;
        ph[j] = rem / 20;
        pw[j] = rem - ph[j] * 20;
    }

    for (int k0 = 0; k0 < 192; k0 += 16) {
#pragma unroll
        for (int i = 0; i < 2; i++) {
            int idx4 = tid * 2 + i;
            int co = idx4 >> 2, k4 = (idx4 & 3) * 4;
            float4 wv = *reinterpret_cast<const float4*>(Wp + co * 192 + k0 + k4);
            Ws[k4 + 0][co] = wv.x; Ws[k4 + 1][co] = wv.y;
            Ws[k4 + 2][co] = wv.z; Ws[k4 + 3][co] = wv.w;
        }
        {
            int kk = k0 + ks;
            int ci = kk / 3;
            int dt = kk - ci * 3 - 1;
#pragma unroll
            for (int j = 0; j < 8; j++) {
                int d = pd[j], h = ph[j], w = pw[j];
                if (cv == 0) h += dt; else if (cv == 1) d += dt; else w += dt;
                unsigned cd = (cv == 0) ? (unsigned)h : ((cv == 1) ? (unsigned)d : (unsigned)w);
                float val = 0.f;
                if (cd < 20u)
                    val = x[((b * CH + ci) * DD + d) * 400 + h * 20 + w];
                Xs[ks][nb + j] = val;
            }
        }
        __syncthreads();
#pragma unroll
        for (int kk = 0; kk < 16; kk++) {
            float4 xr = *reinterpret_cast<const float4*>(&Xs[kk][tn]);
            const uint64_t* wp = reinterpret_cast<const uint64_t*>(&Ws[kk][tc]);
            uint64_t w2[4];
            w2[0] = wp[0]; w2[1] = wp[1]; w2[2] = wp[2]; w2[3] = wp[3];
            uint64_t xb[4];
            asm("mov.b64 %0, {%1,%1};" : "=l"(xb[0]) : "f"(xr.x));
            asm("mov.b64 %0, {%1,%1};" : "=l"(xb[1]) : "f"(xr.y));
            asm("mov.b64 %0, {%1,%1};" : "=l"(xb[2]) : "f"(xr.z));
            asm("mov.b64 %0, {%1,%1};" : "=l"(xb[3]) : "f"(xr.w));
#pragma unroll
            for (int ip = 0; ip < 4; ip++) {
                FMA2(acc2[ip][0], w2[ip], xb[0]);
                FMA2(acc2[ip][1], w2[ip], xb[1]);
                FMA2(acc2[ip][2], w2[ip], xb[2]);
                FMA2(acc2[ip][3], w2[ip], xb[3]);
            }
        }
        __syncthreads();
    }
#pragma unroll
    for (int ip = 0; ip < 4; ip++) {
        float lo[4], hi[4];
#pragma unroll
        for (int j = 0; j < 4; j++)
            asm("mov.b64 {%0,%1}, %2;" : "=f"(lo[j]), "=f"(hi[j]) : "l"(acc2[ip][j]));
#pragma unroll
        for (int half = 0; half < 2; half++) {
            const int co = tc + 2 * ip + half;
            const float bias = Bp[co];
#pragma unroll
            for (int j = 0; j < 4; j++) {
                const int n = n0 + tn + j;
                const float v = (half ? hi[j] : lo[j]) + bias;
                const __half hv = __float2half_rn(v);
                if (cv == 2) {
                    int nl = tn + j;
                    int np = permw(nl >> 1) * 2 + (nl & 1);
                    g_Vh[((size_t)b * CH + co) * NN + n0 + np] = hv;
                } else {
                    int cp = permw(co >> 1) * 2 + (co & 1);
                    (cv ? g_Kh : g_Qh)[((size_t)b * NN + n) * CH + cp] = hv;
                }
            }
        }
    }
}

// ---------------------------------------------------------------------------
// Attention kernel: 256 threads, two key-split groups, 6-stage ring, one
// barrier per tile. Tile body split into two independent k32 (kp) halves so
// QK/exp/PV phases interleave instead of convoying per group.
// ---------------------------------------------------------------------------
__device__ __forceinline__ uint32_t smem_u32(const void* p) {
    uint32_t a;
    asm("{ .reg .u64 t; cvta.to.shared.u64 t, %1; cvt.u32.u64 %0, t; }" : "=r"(a) : "l"(p));
    return a;
}

#define MMA16(d, a, b0_, b1_)                                                 \
    asm volatile("mma.sync.aligned.m16n8k16.row.col.f32.f16.f16.f32 "         \
                 "{%0,%1,%2,%3},{%4,%5,%6,%7},{%8,%9},{%0,%1,%2,%3};"         \
                 : "+f"((d)[0]), "+f"((d)[1]), "+f"((d)[2]), "+f"((d)[3])     \
                 : "r"((a)[0]), "r"((a)[1]), "r"((a)[2]), "r"((a)[3]),        \
                   "r"(b0_), "r"(b1_))

#define CP16(dst, src)                                                        \
    asm volatile("cp.async.cg.shared.global [%0], [%1], 16;" :: "r"(dst), "l"(src))
#define CP_COMMIT() asm volatile("cp.async.commit_group;" ::: "memory")
#define CP_WAIT1()  asm volatile("cp.async.wait_group 1;" ::: "memory")
#define GBAR(id)    asm volatile("bar.sync %0, 128;" :: "r"(id) : "memory")

__device__ __forceinline__ uint4 lds128(uint32_t a) {
    uint4 v;
    asm volatile("ld.shared.v4.b32 {%0,%1,%2,%3}, [%4];"
                 : "=r"(v.x), "=r"(v.y), "=r"(v.z), "=r"(v.w) : "r"(a));
    return v;
}

__device__ __forceinline__ float ex2(float x) {
    float y;
    asm("ex2.approx.ftz.f32 %0, %1;" : "=f"(y) : "f"(x));
    return y;
}
#define LOG2E 1.4426950408889634f
// pack (lo,hi) f32 -> f16x2 with saturate-to-finite (clamps P at half max)
#define CVTPK(d, hi_, lo_)                                                    \
    asm("cvt.rn.satfinite.f16x2.f32 %0, %1, %2;" : "=r"(d) : "f"(hi_), "f"(lo_))

// dynamic smem (bytes): K ring[6] @0 (6x8192=49152), V ring[6] @49152, Q @98304 = 106496
#define KOFF  0
#define VOFF  49152
#define QOFF  98304
#define SMEMSZ 106496
// row swizzle: 16B chunk c at row x stored at c ^ f(x&7)
#define FSW(x) ((((x) & 1) << 2) | (((x) & 7) >> 1))

__global__ __launch_bounds__(256, 2) void attn_kernel(float* __restrict__ out)
{
    extern __shared__ __align__(16) uint8_t sm[];
    const int tid = threadIdx.x;
    const int warp = tid >> 5, lane = tid & 31;
    const int g = lane >> 2, r = lane & 3;
    const int gid = tid >> 7;              // key-split warp group 0/1
    const int wg_tid = tid & 127;
    const int wq = warp & 3;               // warp within group
    const int b = blockIdx.y;
    const int m0 = (int)(((unsigned)blockIdx.x * 7936u) / 147u);  // overlap tiles, 1 wave
    const int mw = wq * 16;

    const uint32_t sb = smem_u32(sm);
    // per-lane swizzled chunk offsets for fragment loads (rows with row&7 == g)
    const int fg = FSW(g);
    const uint32_t co0 = (uint32_t)(((((fg >> 2) ^ 0) << 2) | (r ^ (fg & 3))) * 16);
    const uint32_t co1 = (uint32_t)(((((fg >> 2) ^ 1) << 2) | (r ^ (fg & 3))) * 16);
    const uint32_t gco = (uint32_t)(g * 128);

    // staging ids: 128 threads of a group stage one 64-row tile (64B per thread per tensor)
    const int srow = wg_tid >> 1, hb = wg_tid & 1;
    const int fr = FSW(srow);
    const uint32_t kdst = sb + KOFF + srow * 128;
    const uint32_t vdst = sb + VOFF + srow * 128;
    const uint8_t* kg = (const uint8_t*)g_Kh + ((size_t)b * NN + srow) * 128;
    const uint8_t* vg = (const uint8_t*)g_Vh + ((size_t)(b * CH) + srow) * (NN * 2);

    // prologue: each group stages tiles gid (stage gid) and gid+2 (stage gid+2)
#pragma unroll
    for (int sdx = 0; sdx < 2; sdx++) {
        const int tt = gid + 2 * sdx;
        const uint32_t kd = kdst + tt * 8192;
        const uint32_t vd = vdst + tt * 8192;
        const uint8_t* kgs = kg + (size_t)tt * 8192;
        const uint8_t* vgs = vg + (size_t)tt * 128;
#pragma unroll
        for (int i = 0; i < 4; i++) {
            int c = hb * 4 + i;
            CP16(kd + (uint32_t)((c ^ fr) * 16), kgs + c * 16);
        }
#pragma unroll
        for (int i = 0; i < 4; i++) {
            int c = hb * 4 + i;
            CP16(vd + (uint32_t)((c ^ fr) * 16), vgs + c * 16);
        }
        CP_COMMIT();
    }

    // stage Q tile (64 rows x 128B), all 256 threads
    {
        const int qrow = tid >> 2, qp = tid & 3;
        const int fq = FSW(qrow);
        const uint8_t* qsrc = (const uint8_t*)g_Qh + ((size_t)b * NN + m0 + qrow) * 128;
#pragma unroll
        for (int j2 = 0; j2 < 2; j2++) {
            int j = qp * 2 + j2;
            *reinterpret_cast<uint4*>(sm + QOFF + qrow * 128 + ((j ^ fq) * 16)) =
                *reinterpret_cast<const uint4*>(qsrc + j * 16);
        }
    }
    __syncthreads();

    // persistent Q A-fragments
    uint32_t qa[4][4];
#pragma unroll
    for (int kp = 0; kp < 2; kp++)
#pragma unroll
        for (int h = 0; h < 2; h++) {
            uint4 v = lds128(sb + QOFF + (mw + h * 8 + g) * 128 + (kp ? co1 : co0));
            qa[2 * kp][h]         = v.x;
            qa[2 * kp + 1][h]     = v.y;
            qa[2 * kp][h + 2]     = v.z;
            qa[2 * kp + 1][h + 2] = v.w;
        }

    float oacc[8][4];
#pragma unroll
    for (int i = 0; i < 8; i++)
#pragma unroll
        for (int j = 0; j < 4; j++) oacc[i][j] = 0.f;
    float dacc[4] = {0.f, 0.f, 0.f, 0.f};     // row-sum accumulator (den) via ones-MMA
    const uint32_t bones = 0x3C003C00u;       // half2(1.0, 1.0)

    int st = gid;                            // stage of current tile (tile mod 6)
#pragma unroll 1
    for (int t = gid; t < 125; t += 2) {
        CP_WAIT1();
        GBAR(gid + 1);   // tile t data visible to group; stage st+4's old tile fully read

        // ---- refill stage (st+4) mod 6 with tile t+4 (overlaps compute below) ----
        {
            int pst = st + 4; if (pst >= 6) pst -= 6;
            if (t + 4 < 125) {
                const int tt = t + 4;
                const uint32_t kd = kdst + pst * 8192;
                const uint32_t vd = vdst + pst * 8192;
                const uint8_t* kgs = kg + (size_t)tt * 8192;
                const uint8_t* vgs = vg + (size_t)tt * 128;
#pragma unroll
                for (int i = 0; i < 4; i++) {
                    int c = hb * 4 + i;
                    CP16(kd + (uint32_t)((c ^ fr) * 16), kgs + c * 16);
                }
#pragma unroll
                for (int i = 0; i < 4; i++) {
                    int c = hb * 4 + i;
                    CP16(vd + (uint32_t)((c ^ fr) * 16), vgs + c * 16);
                }
            }
            CP_COMMIT();
        }

        // ---- per-tile fragment base addresses (inner loads are base + imm) ----
        const uint32_t ksg = sb + KOFF + st * 8192 + gco;
        const uint32_t vsg = sb + VOFF + st * 8192 + gco;
        const uint32_t kb0 = ksg + co0, kb1 = ksg + co1;
        const uint32_t vb0 = vsg + co0, vb1 = vsg + co1;

        // ---- two independent k32 halves: QK(kp) -> exp(kp) -> den -> PV(kp) ----
#pragma unroll
        for (int kp = 0; kp < 2; kp++) {
            // QK for key blocks nb = 4kp .. 4kp+3
            float s[4][4];
#pragma unroll
            for (int i = 0; i < 4; i++) {
                const int nb = 4 * kp + i;
#pragma unroll
                for (int j = 0; j < 4; j++) s[i][j] = 0.f;
                uint4 bv0 = lds128(kb0 + nb * 1024);
                MMA16(s[i], qa[0], bv0.x, bv0.z);
                MMA16(s[i], qa[1], bv0.y, bv0.w);
                uint4 bv1 = lds128(kb1 + nb * 1024);
                MMA16(s[i], qa[2], bv1.x, bv1.z);
                MMA16(s[i], qa[3], bv1.y, bv1.w);
            }

            // softmax numerators for this half: exp2(s*log2e - 18), satfinite pack
            uint32_t pa2[2][4];
#pragma unroll
            for (int j = 0; j < 2; j++) {
                float e00 = ex2(fmaf(s[2 * j][0], LOG2E, -18.f));
                float e01 = ex2(fmaf(s[2 * j][1], LOG2E, -18.f));
                float e02 = ex2(fmaf(s[2 * j][2], LOG2E, -18.f));
                float e03 = ex2(fmaf(s[2 * j][3], LOG2E, -18.f));
                float e10 = ex2(fmaf(s[2 * j + 1][0], LOG2E, -18.f));
                float e11 = ex2(fmaf(s[2 * j + 1][1], LOG2E, -18.f));
                float e12 = ex2(fmaf(s[2 * j + 1][2], LOG2E, -18.f));
                float e13 = ex2(fmaf(s[2 * j + 1][3], LOG2E, -18.f));
                CVTPK(pa2[j][0], e01, e00);   // row g,   k-lo
                CVTPK(pa2[j][1], e03, e02);   // row g+8, k-lo
                CVTPK(pa2[j][2], e11, e10);   // row g,   k-hi
                CVTPK(pa2[j][3], e13, e12);   // row g+8, k-hi
            }

            // den: row-sum of this half's P via ones-B MMA
            MMA16(dacc, pa2[0], bones, bones);
            MMA16(dacc, pa2[1], bones, bones);

            // PV for this half: one lds128 per cb covers both k16 chunks of kp
            const uint32_t vbk = kp ? vb1 : vb0;
#pragma unroll
            for (int cb = 0; cb < 8; cb++) {
                uint4 bv = lds128(vbk + cb * 1024);
                MMA16(oacc[cb], pa2[0], bv.x, bv.z);
                MMA16(oacc[cb], pa2[1], bv.y, bv.w);
            }
        }

        st += 2; if (st >= 6) st -= 6;
    }

    float den0 = dacc[0], den1 = dacc[2];    // full row sums (rows g, g+8)

    // ---- merge group B partials into group A via smem (reuse K ring) ----
    __syncthreads();
    const uint32_t scr = sb + KOFF + (uint32_t)((wq * 32 + lane) * 35 * 4);  // 35-word stride
    if (gid == 1) {
#pragma unroll
        for (int i = 0; i < 8; i++)
#pragma unroll
            for (int j = 0; j < 4; j++)
                asm volatile("st.shared.f32 [%0], %1;" :: "r"(scr + (i * 4 + j) * 4), "f"(oacc[i][j]) : "memory");
        asm volatile("st.shared.f32 [%0], %1;" :: "r"(scr + 32 * 4), "f"(den0) : "memory");
        asm volatile("st.shared.f32 [%0], %1;" :: "r"(scr + 33 * 4), "f"(den1) : "memory");
    }
    __syncthreads();
    if (gid == 0) {
#pragma unroll
        for (int i = 0; i < 8; i++)
#pragma unroll
            for (int j = 0; j < 4; j++) {
                float v;
                asm volatile("ld.shared.f32 %0, [%1];" : "=f"(v) : "r"(scr + (i * 4 + j) * 4));
                oacc[i][j] += v;
            }
        float v0, v1;
        asm volatile("ld.shared.f32 %0, [%1];" : "=f"(v0) : "r"(scr + 32 * 4));
        asm volatile("ld.shared.f32 %0, [%1];" : "=f"(v1) : "r"(scr + 33 * 4));
        den0 += v0; den1 += v1;

        const float i0 = 1.f / den0, i1 = 1.f / den1;

        const int m = m0 + mw + g;
#pragma unroll
        for (int cb = 0; cb < 8; cb++) {
            int c = cb * 8 + 2 * r;
            out[((size_t)b * CH + c    ) * NN + m]     = oacc[cb][0] * i0;
            out[((size_t)b * CH + c + 1) * NN + m]     = oacc[cb][1] * i0;
            out[((size_t)b * CH + c    ) * NN + m + 8] = oacc[cb][2] * i1;
            out[((size_t)b * CH + c + 1) * NN + m + 8] = oacc[cb][3] * i1;
        }
    }
}

extern "C" void kernel_launch(void* const* d_in, const int* in_sizes, int n_in,
                              void* d_out, int out_size)
{
    const float* x  = (const float*)d_in[0];
    const float* qw = (const float*)d_in[1];
    const float* qb = (const float*)d_in[2];
    const float* kw = (const float*)d_in[3];
    const float* kb = (const float*)d_in[4];
    const float* vw = (const float*)d_in[5];
    const float* vb = (const float*)d_in[6];
    float* out = (float*)d_out;

    cudaFuncSetAttribute(attn_kernel, cudaFuncAttributeMaxDynamicSharedMemorySize, SMEMSZ);
    conv_kernel<<<dim3(125, 2, 3), 128>>>(x, qw, qb, kw, kb, vw, vb);
    attn_kernel<<<dim3(148, 2), 256, SMEMSZ>>>(out);
}

// round 13
// speedup vs baseline: 2.3143x; 1.0430x over previous
#include <cuda_runtime.h>
#include <cuda_fp16.h>
#include <cstdint>

#define BATCH 2
#define CH    64
#define DD    20
#define NN    8000
#define SK    68

// Projections in fp16. g_Q,g_K: [b][n][c] with channel-words permuted for LDS.128 frags.
// g_V: [b][c][n] with key-words permuted within each 64-block.
__device__ __align__(256) __half g_Qh[BATCH * NN * CH];
__device__ __align__(256) __half g_Kh[BATCH * NN * CH];
__device__ __align__(256) __half g_Vh[BATCH * NN * CH];

#define FMA2(d, a, b_) \
    asm("fma.rn.f32x2 %0, %1, %2, %0;" : "+l"(d) : "l"(a), "l"(b_))

// ---------------------------------------------------------------------------
// Conv kernel: GEMM-style f32x2 compute; output through smem transpose so all
// GMEM stores are coalesced STG.128 (word permutation applied at smem gather).
// ---------------------------------------------------------------------------
__global__ __launch_bounds__(128) void conv_kernel(
    const float* __restrict__ x,
    const float* __restrict__ qw, const float* __restrict__ qb,
    const float* __restrict__ kw, const float* __restrict__ kbias,
    const float* __restrict__ vw, const float* __restrict__ vb)
{
    const int nt = blockIdx.x, b = blockIdx.y, cv = blockIdx.z;
    const float* Wp = (cv == 0) ? qw : ((cv == 1) ? kw : vw);
    const float* Bp = (cv == 0) ? qb : ((cv == 1) ? kbias : vb);
    const int n0 = nt * 64, tid = threadIdx.x;

    __shared__ float Ws[16][SK];
    __shared__ float Xs[16][SK];
    __shared__ __half Os[64][SK];   // output staging: [n][c] (q/k) or [c][n] (v)

    const int tn = (tid & 15) * 4;   // 4 n columns (16B aligned)
    const int tc = (tid >> 4) * 8;   // 8 output channels = 4 pairs

    uint64_t acc2[4][4];             // [channel pair][n col], f32x2 lanes (lo=even co)
#pragma unroll
    for (int ip = 0; ip < 4; ip++)
#pragma unroll
        for (int j = 0; j < 4; j++) acc2[ip][j] = 0ull;

    const int ks = tid >> 3;
    const int nb = (tid & 7) * 8;
    int pd[8], ph[8], pw[8];
#pragma unroll
    for (int j = 0; j < 8; j++) {
        int n = n0 + nb + j;
        pd[j] = n / 400;
        int rem = n - pd[j] * 400;
        ph[j] = rem / 20;
        pw[j] = rem - ph[j] * 20;
    }

    for (int k0 = 0; k0 < 192; k0 += 16) {
#pragma unroll
        for (int i = 0; i < 2; i++) {
            int idx4 = tid * 2 + i;
            int co = idx4 >> 2, k4 = (idx4 & 3) * 4;
            float4 wv = *reinterpret_cast<const float4*>(Wp + co * 192 + k0 + k4);
            Ws[k4 + 0][co] = wv.x; Ws[k4 + 1][co] = wv.y;
            Ws[k4 + 2][co] = wv.z; Ws[k4 + 3][co] = wv.w;
        }
        {
            int kk = k0 + ks;
            int ci = kk / 3;
            int dt = kk - ci * 3 - 1;
#pragma unroll
            for (int j = 0; j < 8; j++) {
                int d = pd[j], h = ph[j], w = pw[j];
                if (cv == 0) h += dt; else if (cv == 1) d += dt; else w += dt;
                unsigned cd = (cv == 0) ? (unsigned)h : ((cv == 1) ? (unsigned)d : (unsigned)w);
                float val = 0.f;
                if (cd < 20u)
                    val = x[((b * CH + ci) * DD + d) * 400 + h * 20 + w];
                Xs[ks][nb + j] = val;
            }
        }
        __syncthreads();
#pragma unroll
        for (int kk = 0; kk < 16; kk++) {
            float4 xr = *reinterpret_cast<const float4*>(&Xs[kk][tn]);
            const uint64_t* wp = reinterpret_cast<const uint64_t*>(&Ws[kk][tc]);
            uint64_t w2[4];
            w2[0] = wp[0]; w2[1] = wp[1]; w2[2] = wp[2]; w2[3] = wp[3];
            uint64_t xb[4];
            asm("mov.b64 %0, {%1,%1};" : "=l"(xb[0]) : "f"(xr.x));
            asm("mov.b64 %0, {%1,%1};" : "=l"(xb[1]) : "f"(xr.y));
            asm("mov.b64 %0, {%1,%1};" : "=l"(xb[2]) : "f"(xr.z));
            asm("mov.b64 %0, {%1,%1};" : "=l"(xb[3]) : "f"(xr.w));
#pragma unroll
            for (int ip = 0; ip < 4; ip++) {
                FMA2(acc2[ip][0], w2[ip], xb[0]);
                FMA2(acc2[ip][1], w2[ip], xb[1]);
                FMA2(acc2[ip][2], w2[ip], xb[2]);
                FMA2(acc2[ip][3], w2[ip], xb[3]);
            }
        }
        __syncthreads();
    }

    // ---- stage results in smem (fp16), natural layout ----
#pragma unroll
    for (int ip = 0; ip < 4; ip++) {
        float lo[4], hi[4];
#pragma unroll
        for (int j = 0; j < 4; j++)
            asm("mov.b64 {%0,%1}, %2;" : "=f"(lo[j]), "=f"(hi[j]) : "l"(acc2[ip][j]));
#pragma unroll
        for (int half = 0; half < 2; half++) {
            const int co = tc + 2 * ip + half;
            const float bias = Bp[co];
#pragma unroll
            for (int j = 0; j < 4; j++) {
                const int nl = tn + j;
                const __half hv = __float2half_rn((half ? hi[j] : lo[j]) + bias);
                if (cv == 2) Os[co][nl] = hv;   // V: row=channel, col=n
                else         Os[nl][co] = hv;   // Q/K: row=n, col=channel
            }
        }
    }
    __syncthreads();

    // ---- coalesced output: each thread gathers 16 permuted words, 4x STG.128 ----
    // dest word position p holds source word w = invperm(p); perm is word-level,
    // low/high half order preserved. Row R = dest row (n for q/k, channel for v).
    {
        const int R = tid >> 1, h4 = tid & 1;
        const uint32_t* Osw = reinterpret_cast<const uint32_t*>(&Os[R][0]);
        __half* dst;
        if (cv == 2) dst = g_Vh + ((size_t)(b * CH + R)) * NN + n0;
        else         dst = (cv ? g_Kh : g_Qh) + ((size_t)(b * NN + n0 + R)) * CH;
        uint32_t wbuf[16];
#pragma unroll
        for (int idx = 0; idx < 16; idx++) {
            const int p = h4 * 16 + idx;
            const int k16 = ((p >> 4) << 1) | (p & 1);
            const int jj = (((p >> 1) & 1) << 2) | ((p >> 2) & 3);
            wbuf[idx] = Osw[k16 * 8 + jj];
        }
        uint4* d4 = reinterpret_cast<uint4*>(dst) + h4 * 4;
#pragma unroll
        for (int c = 0; c < 4; c++)
            d4[c] = make_uint4(wbuf[4 * c], wbuf[4 * c + 1], wbuf[4 * c + 2], wbuf[4 * c + 3]);
    }
}

// ---------------------------------------------------------------------------
// Attention kernel (unchanged from R11): 256 threads, two key-split groups,
// 6-stage ring, one barrier per tile, kp-split tile body.
// ---------------------------------------------------------------------------
__device__ __forceinline__ uint32_t smem_u32(const void* p) {
    uint32_t a;
    asm("{ .reg .u64 t; cvta.to.shared.u64 t, %1; cvt.u32.u64 %0, t; }" : "=r"(a) : "l"(p));
    return a;
}

#define MMA16(d, a, b0_, b1_)                                                 \
    asm volatile("mma.sync.aligned.m16n8k16.row.col.f32.f16.f16.f32 "         \
                 "{%0,%1,%2,%3},{%4,%5,%6,%7},{%8,%9},{%0,%1,%2,%3};"         \
                 : "+f"((d)[0]), "+f"((d)[1]), "+f"((d)[2]), "+f"((d)[3])     \
                 : "r"((a)[0]), "r"((a)[1]), "r"((a)[2]), "r"((a)[3]),        \
                   "r"(b0_), "r"(b1_))

#define CP16(dst, src)                                                        \
    asm volatile("cp.async.cg.shared.global [%0], [%1], 16;" :: "r"(dst), "l"(src))
#define CP_COMMIT() asm volatile("cp.async.commit_group;" ::: "memory")
#define CP_WAIT1()  asm volatile("cp.async.wait_group 1;" ::: "memory")
#define GBAR(id)    asm volatile("bar.sync %0, 128;" :: "r"(id) : "memory")

__device__ __forceinline__ uint4 lds128(uint32_t a) {
    uint4 v;
    asm volatile("ld.shared.v4.b32 {%0,%1,%2,%3}, [%4];"
                 : "=r"(v.x), "=r"(v.y), "=r"(v.z), "=r"(v.w) : "r"(a));
    return v;
}

__device__ __forceinline__ float ex2(float x) {
    float y;
    asm("ex2.approx.ftz.f32 %0, %1;" : "=f"(y) : "f"(x));
    return y;
}
#define LOG2E 1.4426950408889634f
// pack (lo,hi) f32 -> f16x2 with saturate-to-finite (clamps P at half max)
#define CVTPK(d, hi_, lo_)                                                    \
    asm("cvt.rn.satfinite.f16x2.f32 %0, %1, %2;" : "=r"(d) : "f"(hi_), "f"(lo_))

// dynamic smem (bytes): K ring[6] @0 (6x8192=49152), V ring[6] @49152, Q @98304 = 106496
#define KOFF  0
#define VOFF  49152
#define QOFF  98304
#define SMEMSZ 106496
// row swizzle: 16B chunk c at row x stored at c ^ f(x&7)
#define FSW(x) ((((x) & 1) << 2) | (((x) & 7) >> 1))

__global__ __launch_bounds__(256, 2) void attn_kernel(float* __restrict__ out)
{
    extern __shared__ __align__(16) uint8_t sm[];
    const int tid = threadIdx.x;
    const int warp = tid >> 5, lane = tid & 31;
    const int g = lane >> 2, r = lane & 3;
    const int gid = tid >> 7;              // key-split warp group 0/1
    const int wg_tid = tid & 127;
    const int wq = warp & 3;               // warp within group
    const int b = blockIdx.y;
    const int m0 = (int)(((unsigned)blockIdx.x * 7936u) / 147u);  // overlap tiles, 1 wave
    const int mw = wq * 16;

    const uint32_t sb = smem_u32(sm);
    // per-lane swizzled chunk offsets for fragment loads (rows with row&7 == g)
    const int fg = FSW(g);
    const uint32_t co0 = (uint32_t)(((((fg >> 2) ^ 0) << 2) | (r ^ (fg & 3))) * 16);
    const uint32_t co1 = (uint32_t)(((((fg >> 2) ^ 1) << 2) | (r ^ (fg & 3))) * 16);
    const uint32_t gco = (uint32_t)(g * 128);

    // staging ids: 128 threads of a group stage one 64-row tile (64B per thread per tensor)
    const int srow = wg_tid >> 1, hb = wg_tid & 1;
    const int fr = FSW(srow);
    const uint32_t kdst = sb + KOFF + srow * 128;
    const uint32_t vdst = sb + VOFF + srow * 128;
    const uint8_t* kg = (const uint8_t*)g_Kh + ((size_t)b * NN + srow) * 128;
    const uint8_t* vg = (const uint8_t*)g_Vh + ((size_t)(b * CH) + srow) * (NN * 2);

    // prologue: each group stages tiles gid (stage gid) and gid+2 (stage gid+2)
#pragma unroll
    for (int sdx = 0; sdx < 2; sdx++) {
        const int tt = gid + 2 * sdx;
        const uint32_t kd = kdst + tt * 8192;
        const uint32_t vd = vdst + tt * 8192;
        const uint8_t* kgs = kg + (size_t)tt * 8192;
        const uint8_t* vgs = vg + (size_t)tt * 128;
#pragma unroll
        for (int i = 0; i < 4; i++) {
            int c = hb * 4 + i;
            CP16(kd + (uint32_t)((c ^ fr) * 16), kgs + c * 16);
        }
#pragma unroll
        for (int i = 0; i < 4; i++) {
            int c = hb * 4 + i;
            CP16(vd + (uint32_t)((c ^ fr) * 16), vgs + c * 16);
        }
        CP_COMMIT();
    }

    // stage Q tile (64 rows x 128B), all 256 threads
    {
        const int qrow = tid >> 2, qp = tid & 3;
        const int fq = FSW(qrow);
        const uint8_t* qsrc = (const uint8_t*)g_Qh + ((size_t)b * NN + m0 + qrow) * 128;
#pragma unroll
        for (int j2 = 0; j2 < 2; j2++) {
            int j = qp * 2 + j2;
            *reinterpret_cast<uint4*>(sm + QOFF + qrow * 128 + ((j ^ fq) * 16)) =
                *reinterpret_cast<const uint4*>(qsrc + j * 16);
        }
    }
    __syncthreads();

    // persistent Q A-fragments
    uint32_t qa[4][4];
#pragma unroll
    for (int kp = 0; kp < 2; kp++)
#pragma unroll
        for (int h = 0; h < 2; h++) {
            uint4 v = lds128(sb + QOFF + (mw + h * 8 + g) * 128 + (kp ? co1 : co0));
            qa[2 * kp][h]         = v.x;
            qa[2 * kp + 1][h]     = v.y;
            qa[2 * kp][h + 2]     = v.z;
            qa[2 * kp + 1][h + 2] = v.w;
        }

    float oacc[8][4];
#pragma unroll
    for (int i = 0; i < 8; i++)
#pragma unroll
        for (int j = 0; j < 4; j++) oacc[i][j] = 0.f;
    float dacc[4] = {0.f, 0.f, 0.f, 0.f};     // row-sum accumulator (den) via ones-MMA
    const uint32_t bones = 0x3C003C00u;       // half2(1.0, 1.0)

    int st = gid;                            // stage of current tile (tile mod 6)
#pragma unroll 1
    for (int t = gid; t < 125; t += 2) {
        CP_WAIT1();
        GBAR(gid + 1);   // tile t data visible to group; stage st+4's old tile fully read

        // ---- refill stage (st+4) mod 6 with tile t+4 (overlaps compute below) ----
        {
            int pst = st + 4; if (pst >= 6) pst -= 6;
            if (t + 4 < 125) {
                const int tt = t + 4;
                const uint32_t kd = kdst + pst * 8192;
                const uint32_t vd = vdst + pst * 8192;
                const uint8_t* kgs = kg + (size_t)tt * 8192;
                const uint8_t* vgs = vg + (size_t)tt * 128;
#pragma unroll
                for (int i = 0; i < 4; i++) {
                    int c = hb * 4 + i;
                    CP16(kd + (uint32_t)((c ^ fr) * 16), kgs + c * 16);
                }
#pragma unroll
                for (int i = 0; i < 4; i++) {
                    int c = hb * 4 + i;
                    CP16(vd + (uint32_t)((c ^ fr) * 16), vgs + c * 16);
                }
            }
            CP_COMMIT();
        }

        // ---- per-tile fragment base addresses (inner loads are base + imm) ----
        const uint32_t ksg = sb + KOFF + st * 8192 + gco;
        const uint32_t vsg = sb + VOFF + st * 8192 + gco;
        const uint32_t kb0 = ksg + co0, kb1 = ksg + co1;
        const uint32_t vb0 = vsg + co0, vb1 = vsg + co1;

        // ---- two independent k32 halves: QK(kp) -> exp(kp) -> den -> PV(kp) ----
#pragma unroll
        for (int kp = 0; kp < 2; kp++) {
            // QK for key blocks nb = 4kp .. 4kp+3
            float s[4][4];
#pragma unroll
            for (int i = 0; i < 4; i++) {
                const int nb = 4 * kp + i;
#pragma unroll
                for (int j = 0; j < 4; j++) s[i][j] = 0.f;
                uint4 bv0 = lds128(kb0 + nb * 1024);
                MMA16(s[i], qa[0], bv0.x, bv0.z);
                MMA16(s[i], qa[1], bv0.y, bv0.w);
                uint4 bv1 = lds128(kb1 + nb * 1024);
                MMA16(s[i], qa[2], bv1.x, bv1.z);
                MMA16(s[i], qa[3], bv1.y, bv1.w);
            }

            // softmax numerators for this half: exp2(s*log2e - 18), satfinite pack
            uint32_t pa2[2][4];
#pragma unroll
            for (int j = 0; j < 2; j++) {
                float e00 = ex2(fmaf(s[2 * j][0], LOG2E, -18.f));
                float e01 = ex2(fmaf(s[2 * j][1], LOG2E, -18.f));
                float e02 = ex2(fmaf(s[2 * j][2], LOG2E, -18.f));
                float e03 = ex2(fmaf(s[2 * j][3], LOG2E, -18.f));
                float e10 = ex2(fmaf(s[2 * j + 1][0], LOG2E, -18.f));
                float e11 = ex2(fmaf(s[2 * j + 1][1], LOG2E, -18.f));
                float e12 = ex2(fmaf(s[2 * j + 1][2], LOG2E, -18.f));
                float e13 = ex2(fmaf(s[2 * j + 1][3], LOG2E, -18.f));
                CVTPK(pa2[j][0], e01, e00);   // row g,   k-lo
                CVTPK(pa2[j][1], e03, e02);   // row g+8, k-lo
                CVTPK(pa2[j][2], e11, e10);   // row g,   k-hi
                CVTPK(pa2[j][3], e13, e12);   // row g+8, k-hi
            }

            // den: row-sum of this half's P via ones-B MMA
            MMA16(dacc, pa2[0], bones, bones);
            MMA16(dacc, pa2[1], bones, bones);

            // PV for this half: one lds128 per cb covers both k16 chunks of kp
            const uint32_t vbk = kp ? vb1 : vb0;
#pragma unroll
            for (int cb = 0; cb < 8; cb++) {
                uint4 bv = lds128(vbk + cb * 1024);
                MMA16(oacc[cb], pa2[0], bv.x, bv.z);
                MMA16(oacc[cb], pa2[1], bv.y, bv.w);
            }
        }

        st += 2; if (st >= 6) st -= 6;
    }

    float den0 = dacc[0], den1 = dacc[2];    // full row sums (rows g, g+8)

    // ---- merge group B partials into group A via smem (reuse K ring) ----
    __syncthreads();
    const uint32_t scr = sb + KOFF + (uint32_t)((wq * 32 + lane) * 35 * 4);  // 35-word stride
    if (gid == 1) {
#pragma unroll
        for (int i = 0; i < 8; i++)
#pragma unroll
            for (int j = 0; j < 4; j++)
                asm volatile("st.shared.f32 [%0], %1;" :: "r"(scr + (i * 4 + j) * 4), "f"(oacc[i][j]) : "memory");
        asm volatile("st.shared.f32 [%0], %1;" :: "r"(scr + 32 * 4), "f"(den0) : "memory");
        asm volatile("st.shared.f32 [%0], %1;" :: "r"(scr + 33 * 4), "f"(den1) : "memory");
    }
    __syncthreads();
    if (gid == 0) {
#pragma unroll
        for (int i = 0; i < 8; i++)
#pragma unroll
            for (int j = 0; j < 4; j++) {
                float v;
                asm volatile("ld.shared.f32 %0, [%1];" : "=f"(v) : "r"(scr + (i * 4 + j) * 4));
                oacc[i][j] += v;
            }
        float v0, v1;
        asm volatile("ld.shared.f32 %0, [%1];" : "=f"(v0) : "r"(scr + 32 * 4));
        asm volatile("ld.shared.f32 %0, [%1];" : "=f"(v1) : "r"(scr + 33 * 4));
        den0 += v0; den1 += v1;

        const float i0 = 1.f / den0, i1 = 1.f / den1;

        const int m = m0 + mw + g;
#pragma unroll
        for (int cb = 0; cb < 8; cb++) {
            int c = cb * 8 + 2 * r;
            out[((size_t)b * CH + c    ) * NN + m]     = oacc[cb][0] * i0;
            out[((size_t)b * CH + c + 1) * NN + m]     = oacc[cb][1] * i0;
            out[((size_t)b * CH + c    ) * NN + m + 8] = oacc[cb][2] * i1;
            out[((size_t)b * CH + c + 1) * NN + m + 8] = oacc[cb][3] * i1;
        }
    }
}

extern "C" void kernel_launch(void* const* d_in, const int* in_sizes, int n_in,
                              void* d_out, int out_size)
{
    const float* x  = (const float*)d_in[0];
    const float* qw = (const float*)d_in[1];
    const float* qb = (const float*)d_in[2];
    const float* kw = (const float*)d_in[3];
    const float* kb = (const float*)d_in[4];
    const float* vw = (const float*)d_in[5];
    const float* vb = (const float*)d_in[6];
    float* out = (float*)d_out;

    cudaFuncSetAttribute(attn_kernel, cudaFuncAttributeMaxDynamicSharedMemorySize, SMEMSZ);
    conv_kernel<<<dim3(125, 2, 3), 128>>>(x, qw, qb, kw, kb, vw, vb);
    attn_kernel<<<dim3(148, 2), 256, SMEMSZ>>>(out);
}

// round 14
// speedup vs baseline: 2.6090x; 1.1273x over previous
#include <cuda_runtime.h>
#include <cuda_fp16.h>
#include <cstdint>

#define BATCH 2
#define CH    64
#define DD    20
#define NN    8000
#define SK    68

// Projections in fp16. g_Q,g_K: [b][n][c] with channel-words permuted for LDS.128 frags.
// g_V: [b][c][n] with key-words permuted within each 64-block.
__device__ __align__(256) __half g_Qh[BATCH * NN * CH];
__device__ __align__(256) __half g_Kh[BATCH * NN * CH];
__device__ __align__(256) __half g_Vh[BATCH * NN * CH];

#define FMA2(d, a, b_) \
    asm("fma.rn.f32x2 %0, %1, %2, %0;" : "+l"(d) : "l"(a), "l"(b_))

// ---------------------------------------------------------------------------
// Conv kernel (unchanged from R12/R13): f32x2 compute, smem-transposed output.
// ---------------------------------------------------------------------------
__global__ __launch_bounds__(128) void conv_kernel(
    const float* __restrict__ x,
    const float* __restrict__ qw, const float* __restrict__ qb,
    const float* __restrict__ kw, const float* __restrict__ kbias,
    const float* __restrict__ vw, const float* __restrict__ vb)
{
    const int nt = blockIdx.x, b = blockIdx.y, cv = blockIdx.z;
    const float* Wp = (cv == 0) ? qw : ((cv == 1) ? kw : vw);
    const float* Bp = (cv == 0) ? qb : ((cv == 1) ? kbias : vb);
    const int n0 = nt * 64, tid = threadIdx.x;

    __shared__ float Ws[16][SK];
    __shared__ float Xs[16][SK];
    __shared__ __half Os[64][SK];   // output staging: [n][c] (q/k) or [c][n] (v)

    const int tn = (tid & 15) * 4;
    const int tc = (tid >> 4) * 8;

    uint64_t acc2[4][4];
#pragma unroll
    for (int ip = 0; ip < 4; ip++)
#pragma unroll
        for (int j = 0; j < 4; j++) acc2[ip][j] = 0ull;

    const int ks = tid >> 3;
    const int nb = (tid & 7) * 8;
    int pd[8], ph[8], pw[8];
#pragma unroll
    for (int j = 0; j < 8; j++) {
        int n = n0 + nb + j;
        pd[j] = n / 400;
        int rem = n - pd[j] * 400;
        ph[j] = rem / 20;
        pw[j] = rem - ph[j] * 20;
    }

    for (int k0 = 0; k0 < 192; k0 += 16) {
#pragma unroll
        for (int i = 0; i < 2; i++) {
            int idx4 = tid * 2 + i;
            int co = idx4 >> 2, k4 = (idx4 & 3) * 4;
            float4 wv = *reinterpret_cast<const float4*>(Wp + co * 192 + k0 + k4);
            Ws[k4 + 0][co] = wv.x; Ws[k4 + 1][co] = wv.y;
            Ws[k4 + 2][co] = wv.z; Ws[k4 + 3][co] = wv.w;
        }
        {
            int kk = k0 + ks;
            int ci = kk / 3;
            int dt = kk - ci * 3 - 1;
#pragma unroll
            for (int j = 0; j < 8; j++) {
                int d = pd[j], h = ph[j], w = pw[j];
                if (cv == 0) h += dt; else if (cv == 1) d += dt; else w += dt;
                unsigned cd = (cv == 0) ? (unsigned)h : ((cv == 1) ? (unsigned)d : (unsigned)w);
                float val = 0.f;
                if (cd < 20u)
                    val = x[((b * CH + ci) * DD + d) * 400 + h * 20 + w];
                Xs[ks][nb + j] = val;
            }
        }
        __syncthreads();
#pragma unroll
        for (int kk = 0; kk < 16; kk++) {
            float4 xr = *reinterpret_cast<const float4*>(&Xs[kk][tn]);
            const uint64_t* wp = reinterpret_cast<const uint64_t*>(&Ws[kk][tc]);
            uint64_t w2[4];
            w2[0] = wp[0]; w2[1] = wp[1]; w2[2] = wp[2]; w2[3] = wp[3];
            uint64_t xb[4];
            asm("mov.b64 %0, {%1,%1};" : "=l"(xb[0]) : "f"(xr.x));
            asm("mov.b64 %0, {%1,%1};" : "=l"(xb[1]) : "f"(xr.y));
            asm("mov.b64 %0, {%1,%1};" : "=l"(xb[2]) : "f"(xr.z));
            asm("mov.b64 %0, {%1,%1};" : "=l"(xb[3]) : "f"(xr.w));
#pragma unroll
            for (int ip = 0; ip < 4; ip++) {
                FMA2(acc2[ip][0], w2[ip], xb[0]);
                FMA2(acc2[ip][1], w2[ip], xb[1]);
                FMA2(acc2[ip][2], w2[ip], xb[2]);
                FMA2(acc2[ip][3], w2[ip], xb[3]);
            }
        }
        __syncthreads();
    }

#pragma unroll
    for (int ip = 0; ip < 4; ip++) {
        float lo[4], hi[4];
#pragma unroll
        for (int j = 0; j < 4; j++)
            asm("mov.b64 {%0,%1}, %2;" : "=f"(lo[j]), "=f"(hi[j]) : "l"(acc2[ip][j]));
#pragma unroll
        for (int half = 0; half < 2; half++) {
            const int co = tc + 2 * ip + half;
            const float bias = Bp[co];
#pragma unroll
            for (int j = 0; j < 4; j++) {
                const int nl = tn + j;
                const __half hv = __float2half_rn((half ? hi[j] : lo[j]) + bias);
                if (cv == 2) Os[co][nl] = hv;
                else         Os[nl][co] = hv;
            }
        }
    }
    __syncthreads();

    {
        const int R = tid >> 1, h4 = tid & 1;
        const uint32_t* Osw = reinterpret_cast<const uint32_t*>(&Os[R][0]);
        __half* dst;
        if (cv == 2) dst = g_Vh + ((size_t)(b * CH + R)) * NN + n0;
        else         dst = (cv ? g_Kh : g_Qh) + ((size_t)(b * NN + n0 + R)) * CH;
        uint32_t wbuf[16];
#pragma unroll
        for (int idx = 0; idx < 16; idx++) {
            const int p = h4 * 16 + idx;
            const int k16 = ((p >> 4) << 1) | (p & 1);
            const int jj = (((p >> 1) & 1) << 2) | ((p >> 2) & 3);
            wbuf[idx] = Osw[k16 * 8 + jj];
        }
        uint4* d4 = reinterpret_cast<uint4*>(dst) + h4 * 4;
#pragma unroll
        for (int c = 0; c < 4; c++)
            d4[c] = make_uint4(wbuf[4 * c], wbuf[4 * c + 1], wbuf[4 * c + 2], wbuf[4 * c + 3]);
    }
}

// ---------------------------------------------------------------------------
// Attention kernel: m32 per warp (two m16 strips), 256 threads, 1 CTA/SM,
// two key-split groups, 6-stage ring, one barrier per tile, kp-split body.
// Every K/V B-fragment LDS feeds both strips (2x HMMA per LDS).
// ---------------------------------------------------------------------------
__device__ __forceinline__ uint32_t smem_u32(const void* p) {
    uint32_t a;
    asm("{ .reg .u64 t; cvta.to.shared.u64 t, %1; cvt.u32.u64 %0, t; }" : "=r"(a) : "l"(p));
    return a;
}

#define MMA16(d, a, b0_, b1_)                                                 \
    asm volatile("mma.sync.aligned.m16n8k16.row.col.f32.f16.f16.f32 "         \
                 "{%0,%1,%2,%3},{%4,%5,%6,%7},{%8,%9},{%0,%1,%2,%3};"         \
                 : "+f"((d)[0]), "+f"((d)[1]), "+f"((d)[2]), "+f"((d)[3])     \
                 : "r"((a)[0]), "r"((a)[1]), "r"((a)[2]), "r"((a)[3]),        \
                   "r"(b0_), "r"(b1_))

#define CP16(dst, src)                                                        \
    asm volatile("cp.async.cg.shared.global [%0], [%1], 16;" :: "r"(dst), "l"(src))
#define CP_COMMIT() asm volatile("cp.async.commit_group;" ::: "memory")
#define CP_WAIT1()  asm volatile("cp.async.wait_group 1;" ::: "memory")
#define GBAR(id)    asm volatile("bar.sync %0, 128;" :: "r"(id) : "memory")

__device__ __forceinline__ uint4 lds128(uint32_t a) {
    uint4 v;
    asm volatile("ld.shared.v4.b32 {%0,%1,%2,%3}, [%4];"
                 : "=r"(v.x), "=r"(v.y), "=r"(v.z), "=r"(v.w) : "r"(a));
    return v;
}

__device__ __forceinline__ float ex2(float x) {
    float y;
    asm("ex2.approx.ftz.f32 %0, %1;" : "=f"(y) : "f"(x));
    return y;
}
#define LOG2E 1.4426950408889634f
#define CVTPK(d, hi_, lo_)                                                    \
    asm("cvt.rn.satfinite.f16x2.f32 %0, %1, %2;" : "=r"(d) : "f"(hi_), "f"(lo_))

// dynamic smem (bytes): K ring[6] @0 (49152), V ring[6] @49152, Q(128 rows) @98304 (16384)
#define KOFF  0
#define VOFF  49152
#define QOFF  98304
#define SMEMSZ 114688
#define FSW(x) ((((x) & 1) << 2) | (((x) & 7) >> 1))

__global__ __launch_bounds__(256, 1) void attn_kernel(float* __restrict__ out)
{
    extern __shared__ __align__(16) uint8_t sm[];
    const int tid = threadIdx.x;
    const int warp = tid >> 5, lane = tid & 31;
    const int g = lane >> 2, r = lane & 3;
    const int gid = tid >> 7;              // key-split warp group 0/1
    const int wg_tid = tid & 127;
    const int wq = warp & 3;               // warp within group
    const int b = blockIdx.y;
    const int m0 = (int)(((unsigned)blockIdx.x * 7872u) / 73u);  // overlap m128 tiles, 1/SM
    const int mw = wq * 16;                // strip0 row base; strip1 = mw + 64

    const uint32_t sb = smem_u32(sm);
    const int fg = FSW(g);
    const uint32_t co0 = (uint32_t)(((((fg >> 2) ^ 0) << 2) | (r ^ (fg & 3))) * 16);
    const uint32_t co1 = (uint32_t)(((((fg >> 2) ^ 1) << 2) | (r ^ (fg & 3))) * 16);
    const uint32_t gco = (uint32_t)(g * 128);

    // staging ids: 128 threads of a group stage one 64-row tile (64B per thread per tensor)
    const int srow = wg_tid >> 1, hb = wg_tid & 1;
    const int fr = FSW(srow);
    const uint32_t kdst = sb + KOFF + srow * 128;
    const uint32_t vdst = sb + VOFF + srow * 128;
    const uint8_t* kg = (const uint8_t*)g_Kh + ((size_t)b * NN + srow) * 128;
    const uint8_t* vg = (const uint8_t*)g_Vh + ((size_t)(b * CH) + srow) * (NN * 2);

    // prologue: each group stages tiles gid (stage gid) and gid+2 (stage gid+2)
#pragma unroll
    for (int sdx = 0; sdx < 2; sdx++) {
        const int tt = gid + 2 * sdx;
        const uint32_t kd = kdst + tt * 8192;
        const uint32_t vd = vdst + tt * 8192;
        const uint8_t* kgs = kg + (size_t)tt * 8192;
        const uint8_t* vgs = vg + (size_t)tt * 128;
#pragma unroll
        for (int i = 0; i < 4; i++) {
            int c = hb * 4 + i;
            CP16(kd + (uint32_t)((c ^ fr) * 16), kgs + c * 16);
        }
#pragma unroll
        for (int i = 0; i < 4; i++) {
            int c = hb * 4 + i;
            CP16(vd + (uint32_t)((c ^ fr) * 16), vgs + c * 16);
        }
        CP_COMMIT();
    }

    // stage Q tile (128 rows x 128B): each thread stages 64B of one row
    {
        const int qrow = tid >> 1, h4 = tid & 1;
        const int fq = FSW(qrow);
        const uint8_t* qsrc = (const uint8_t*)g_Qh + ((size_t)b * NN + m0 + qrow) * 128;
#pragma unroll
        for (int j = 0; j < 4; j++) {
            int c = h4 * 4 + j;
            *reinterpret_cast<uint4*>(sm + QOFF + qrow * 128 + ((c ^ fq) * 16)) =
                *reinterpret_cast<const uint4*>(qsrc + c * 16);
        }
    }
    __syncthreads();

    // persistent Q A-fragments for both strips
    uint32_t qa[2][4][4];
#pragma unroll
    for (int s = 0; s < 2; s++)
#pragma unroll
        for (int kp = 0; kp < 2; kp++)
#pragma unroll
            for (int h = 0; h < 2; h++) {
                uint4 v = lds128(sb + QOFF + (mw + s * 64 + h * 8 + g) * 128 + (kp ? co1 : co0));
                qa[s][2 * kp][h]         = v.x;
                qa[s][2 * kp + 1][h]     = v.y;
                qa[s][2 * kp][h + 2]     = v.z;
                qa[s][2 * kp + 1][h + 2] = v.w;
            }

    float oacc[2][8][4];
#pragma unroll
    for (int s = 0; s < 2; s++)
#pragma unroll
        for (int i = 0; i < 8; i++)
#pragma unroll
            for (int j = 0; j < 4; j++) oacc[s][i][j] = 0.f;
    float dacc[2][4] = {{0.f, 0.f, 0.f, 0.f}, {0.f, 0.f, 0.f, 0.f}};
    const uint32_t bones = 0x3C003C00u;

    int st = gid;
#pragma unroll 1
    for (int t = gid; t < 125; t += 2) {
        CP_WAIT1();
        GBAR(gid + 1);

        // refill stage (st+4) mod 6 with tile t+4 (overlaps compute below)
        {
            int pst = st + 4; if (pst >= 6) pst -= 6;
            if (t + 4 < 125) {
                const int tt = t + 4;
                const uint32_t kd = kdst + pst * 8192;
                const uint32_t vd = vdst + pst * 8192;
                const uint8_t* kgs = kg + (size_t)tt * 8192;
                const uint8_t* vgs = vg + (size_t)tt * 128;
#pragma unroll
                for (int i = 0; i < 4; i++) {
                    int c = hb * 4 + i;
                    CP16(kd + (uint32_t)((c ^ fr) * 16), kgs + c * 16);
                }
#pragma unroll
                for (int i = 0; i < 4; i++) {
                    int c = hb * 4 + i;
                    CP16(vd + (uint32_t)((c ^ fr) * 16), vgs + c * 16);
                }
            }
            CP_COMMIT();
        }

        const uint32_t ksg = sb + KOFF + st * 8192 + gco;
        const uint32_t vsg = sb + VOFF + st * 8192 + gco;
        const uint32_t kb0 = ksg + co0, kb1 = ksg + co1;
        const uint32_t vb0 = vsg + co0, vb1 = vsg + co1;

        // two independent k32 halves; each B fragment feeds BOTH strips
#pragma unroll
        for (int kp = 0; kp < 2; kp++) {
            float s0[4][4], s1[4][4];
#pragma unroll
            for (int i = 0; i < 4; i++) {
                const int nb = 4 * kp + i;
#pragma unroll
                for (int j = 0; j < 4; j++) { s0[i][j] = 0.f; s1[i][j] = 0.f; }
                uint4 bv0 = lds128(kb0 + nb * 1024);
                MMA16(s0[i], qa[0][0], bv0.x, bv0.z);
                MMA16(s0[i], qa[0][1], bv0.y, bv0.w);
                MMA16(s1[i], qa[1][0], bv0.x, bv0.z);
                MMA16(s1[i], qa[1][1], bv0.y, bv0.w);
                uint4 bv1 = lds128(kb1 + nb * 1024);
                MMA16(s0[i], qa[0][2], bv1.x, bv1.z);
                MMA16(s0[i], qa[0][3], bv1.y, bv1.w);
                MMA16(s1[i], qa[1][2], bv1.x, bv1.z);
                MMA16(s1[i], qa[1][3], bv1.y, bv1.w);
            }

            uint32_t pa0[2][4], pa1[2][4];
#pragma unroll
            for (int j = 0; j < 2; j++) {
                float e00 = ex2(fmaf(s0[2 * j][0], LOG2E, -18.f));
                float e01 = ex2(fmaf(s0[2 * j][1], LOG2E, -18.f));
                float e02 = ex2(fmaf(s0[2 * j][2], LOG2E, -18.f));
                float e03 = ex2(fmaf(s0[2 * j][3], LOG2E, -18.f));
                float e10 = ex2(fmaf(s0[2 * j + 1][0], LOG2E, -18.f));
                float e11 = ex2(fmaf(s0[2 * j + 1][1], LOG2E, -18.f));
                float e12 = ex2(fmaf(s0[2 * j + 1][2], LOG2E, -18.f));
                float e13 = ex2(fmaf(s0[2 * j + 1][3], LOG2E, -18.f));
                CVTPK(pa0[j][0], e01, e00);
                CVTPK(pa0[j][1], e03, e02);
                CVTPK(pa0[j][2], e11, e10);
                CVTPK(pa0[j][3], e13, e12);
                float f00 = ex2(fmaf(s1[2 * j][0], LOG2E, -18.f));
                float f01 = ex2(fmaf(s1[2 * j][1], LOG2E, -18.f));
                float f02 = ex2(fmaf(s1[2 * j][2], LOG2E, -18.f));
                float f03 = ex2(fmaf(s1[2 * j][3], LOG2E, -18.f));
                float f10 = ex2(fmaf(s1[2 * j + 1][0], LOG2E, -18.f));
                float f11 = ex2(fmaf(s1[2 * j + 1][1], LOG2E, -18.f));
                float f12 = ex2(fmaf(s1[2 * j + 1][2], LOG2E, -18.f));
                float f13 = ex2(fmaf(s1[2 * j + 1][3], LOG2E, -18.f));
                CVTPK(pa1[j][0], f01, f00);
                CVTPK(pa1[j][1], f03, f02);
                CVTPK(pa1[j][2], f11, f10);
                CVTPK(pa1[j][3], f13, f12);
            }

            MMA16(dacc[0], pa0[0], bones, bones);
            MMA16(dacc[0], pa0[1], bones, bones);
            MMA16(dacc[1], pa1[0], bones, bones);
            MMA16(dacc[1], pa1[1], bones, bones);

            const uint32_t vbk = kp ? vb1 : vb0;
#pragma unroll
            for (int cb = 0; cb < 8; cb++) {
                uint4 bv = lds128(vbk + cb * 1024);
                MMA16(oacc[0][cb], pa0[0], bv.x, bv.z);
                MMA16(oacc[0][cb], pa0[1], bv.y, bv.w);
                MMA16(oacc[1][cb], pa1[0], bv.x, bv.z);
                MMA16(oacc[1][cb], pa1[1], bv.y, bv.w);
            }
        }

        st += 2; if (st >= 6) st -= 6;
    }

    // ---- merge group B partials into group A via smem (reuse K+V rings) ----
    __syncthreads();
    const uint32_t scr = sb + KOFF + (uint32_t)((wq * 32 + lane) * 69 * 4);  // 69-word stride
    if (gid == 1) {
#pragma unroll
        for (int s = 0; s < 2; s++) {
#pragma unroll
            for (int i = 0; i < 8; i++)
#pragma unroll
                for (int j = 0; j < 4; j++)
                    asm volatile("st.shared.f32 [%0], %1;"
                                 :: "r"(scr + (s * 34 + i * 4 + j) * 4), "f"(oacc[s][i][j]) : "memory");
            asm volatile("st.shared.f32 [%0], %1;" :: "r"(scr + (s * 34 + 32) * 4), "f"(dacc[s][0]) : "memory");
            asm volatile("st.shared.f32 [%0], %1;" :: "r"(scr + (s * 34 + 33) * 4), "f"(dacc[s][2]) : "memory");
        }
    }
    __syncthreads();
    if (gid == 0) {
#pragma unroll
        for (int s = 0; s < 2; s++) {
#pragma unroll
            for (int i = 0; i < 8; i++)
#pragma unroll
                for (int j = 0; j < 4; j++) {
                    float v;
                    asm volatile("ld.shared.f32 %0, [%1];" : "=f"(v) : "r"(scr + (s * 34 + i * 4 + j) * 4));
                    oacc[s][i][j] += v;
                }
            float v0, v1;
            asm volatile("ld.shared.f32 %0, [%1];" : "=f"(v0) : "r"(scr + (s * 34 + 32) * 4));
            asm volatile("ld.shared.f32 %0, [%1];" : "=f"(v1) : "r"(scr + (s * 34 + 33) * 4));
            const float den0 = dacc[s][0] + v0, den1 = dacc[s][2] + v1;
            const float i0 = 1.f / den0, i1 = 1.f / den1;

            const int m = m0 + mw + s * 64 + g;
#pragma unroll
            for (int cb = 0; cb < 8; cb++) {
                int c = cb * 8 + 2 * r;
                out[((size_t)b * CH + c    ) * NN + m]     = oacc[s][cb][0] * i0;
                out[((size_t)b * CH + c + 1) * NN + m]     = oacc[s][cb][1] * i0;
                out[((size_t)b * CH + c    ) * NN + m + 8] = oacc[s][cb][2] * i1;
                out[((size_t)b * CH + c + 1) * NN + m + 8] = oacc[s][cb][3] * i1;
            }
        }
    }
}

extern "C" void kernel_launch(void* const* d_in, const int* in_sizes, int n_in,
                              void* d_out, int out_size)
{
    const float* x  = (const float*)d_in[0];
    const float* qw = (const float*)d_in[1];
    const float* qb = (const float*)d_in[2];
    const float* kw = (const float*)d_in[3];
    const float* kb = (const float*)d_in[4];
    const float* vw = (const float*)d_in[5];
    const float* vb = (const float*)d_in[6];
    float* out = (float*)d_out;

    cudaFuncSetAttribute(attn_kernel, cudaFuncAttributeMaxDynamicSharedMemorySize, SMEMSZ);
    conv_kernel<<<dim3(125, 2, 3), 128>>>(x, qw, qb, kw, kb, vw, vb);
    attn_kernel<<<dim3(74, 2), 256, SMEMSZ>>>(out);
}